// round 9
// baseline (speedup 1.0000x reference)
#include <cuda_runtime.h>
#include <cuda_bf16.h>
#include <math.h>

#define NN    50000
#define EE    800000
#define DIN   300
#define DH    96
#define DOUT  2
#define GG    64
#define SCB   196                    // scan blocks: ceil(50000/256)

// ---------------- scratch (device globals; no allocation allowed) -----------
__device__ float g_dis[NN];
__device__ float g_h  [(size_t)NN * DH];    // h * dis (pre-scaled!)
__device__ float g_agg[(size_t)NN * DH];
__device__ float g_pool[GG * DH];
__device__ float g_cnt [GG];
__device__ __nv_bfloat16 g_W1h[DIN * DH], g_W1l[DIN * DH];
__device__ __nv_bfloat16 g_W2h[DH * DH],  g_W2l[DH * DH];
// CSR scratch
__device__ int      g_ncnt[NN];
__device__ int      g_tmp [NN];
__device__ int      g_bsum[256];
__device__ int      g_noff[NN + 1];
__device__ int      g_ncur[NN];
__device__ unsigned g_esrc[EE];      // src ids sorted by dst

// ---------------- weight split + init ---------------------------------------
__global__ void k_wsplit(const float* __restrict__ W1, const float* __restrict__ W2) {
    int i = blockIdx.x * blockDim.x + threadIdx.x;
    if (i < DIN * DH) {
        float f = W1[i];
        __nv_bfloat16 hi = __float2bfloat16(f);
        g_W1h[i] = hi;
        g_W1l[i] = __float2bfloat16(f - __bfloat162float(hi));
    }
    if (i < DH * DH) {
        float f = W2[i];
        __nv_bfloat16 hi = __float2bfloat16(f);
        g_W2h[i] = hi;
        g_W2l[i] = __float2bfloat16(f - __bfloat162float(hi));
    }
    if (i < NN) g_ncnt[i] = 0;
    if (i < GG * DH) g_pool[i] = 0.0f;
    if (i < GG)      g_cnt[i]  = 0.0f;
}
__global__ void k_deg_count(const int* __restrict__ dst) {
    int e = blockIdx.x * blockDim.x + threadIdx.x;
    if (e < EE) atomicAdd(&g_ncnt[dst[e]], 1);
}

// ---------------- scan (dis fused into C) ------------------------------------
__global__ void __launch_bounds__(256) k_scanA() {
    __shared__ int sh[256];
    int t  = threadIdx.x;
    int gi = blockIdx.x * 256 + t;
    int v  = (gi < NN) ? g_ncnt[gi] : 0;
    sh[t] = v; __syncthreads();
#pragma unroll
    for (int off = 1; off < 256; off <<= 1) {
        int u = (t >= off) ? sh[t - off] : 0;
        __syncthreads();
        sh[t] += u;
        __syncthreads();
    }
    if (gi < NN) g_tmp[gi] = sh[t];                   // inclusive within block
    if (t == 255) g_bsum[blockIdx.x] = sh[255];
}
__global__ void __launch_bounds__(256) k_scanC() {
    __shared__ int sb[256];
    int t = threadIdx.x;
    sb[t] = (t < SCB) ? g_bsum[t] : 0;
    __syncthreads();
#pragma unroll
    for (int off = 1; off < 256; off <<= 1) {
        int u = (t >= off) ? sb[t - off] : 0;
        __syncthreads();
        sb[t] += u;
        __syncthreads();
    }
    int gi = blockIdx.x * 256 + t;
    if (gi >= NN) return;
    int base = (blockIdx.x > 0) ? sb[blockIdx.x - 1] : 0;
    int cnt  = g_ncnt[gi];
    int inc  = g_tmp[gi] + base;
    g_noff[gi + 1] = inc;
    g_ncur[gi]     = inc - cnt;
    g_dis[gi]      = rsqrtf(1.0f + (float)cnt);       // fused deg_finish
    if (gi == 0) g_noff[0] = 0;
}
__global__ void __launch_bounds__(256)
k_reorder(const int* __restrict__ src, const int* __restrict__ dst) {
    int e = blockIdx.x * blockDim.x + threadIdx.x;
    if (e >= EE) return;
    int pos = atomicAdd(&g_ncur[dst[e]], 1);
    g_esrc[pos] = (unsigned)src[e];
}

// ---------------- mma helpers ------------------------------------------------
__device__ __forceinline__ unsigned smem_u32(const void* p) {
    return (unsigned)__cvta_generic_to_shared(p);
}
#define LDSM_X4(r, addr) \
    asm volatile("ldmatrix.sync.aligned.m8n8.x4.shared.b16 {%0,%1,%2,%3},[%4];" \
                 : "=r"((r)[0]), "=r"((r)[1]), "=r"((r)[2]), "=r"((r)[3]) : "r"(addr))
#define LDSM_X2_T(r, addr) \
    asm volatile("ldmatrix.sync.aligned.m8n8.x2.trans.shared.b16 {%0,%1},[%2];" \
                 : "=r"((r)[0]), "=r"((r)[1]) : "r"(addr))
#define MMA_BF16(d, a, b) \
    asm volatile("mma.sync.aligned.m16n8k16.row.col.f32.bf16.bf16.f32 " \
                 "{%0,%1,%2,%3},{%4,%5,%6,%7},{%8,%9},{%0,%1,%2,%3};" \
                 : "+f"((d)[0]), "+f"((d)[1]), "+f"((d)[2]), "+f"((d)[3]) \
                 : "r"((a)[0]), "r"((a)[1]), "r"((a)[2]), "r"((a)[3]), \
                   "r"((b)[0]), "r"((b)[1]))

// ---------------- pipelined bf16-split tensor GEMM: out = in @ W ------------
// BM=128 BN=96 BK=16, 8 warps (4Mx2N). Double-buffered smem, TWO-stage-ahead
// register prefetch (covers DRAM latency). Epilogue: g_h = acc*dis,
// g_agg = acc*dis^2.
template <int K, bool RELU_BIAS, bool IN_IS_AGG, int WSEL>
__global__ void __launch_bounds__(256, 2)
k_gemm(const float* __restrict__ in, const float* __restrict__ bias)
{
    __shared__ __nv_bfloat16 Ah[2][128 * 24], Al[2][128 * 24];
    __shared__ __nv_bfloat16 Bh[2][16 * 104], Bl[2][16 * 104];
    __shared__ float bs[DH];

    const int tid  = threadIdx.x;
    const int lane = tid & 31;
    const int wid  = tid >> 5;
    const int wm   = wid & 3;
    const int wn   = wid >> 2;
    const int r0   = blockIdx.x * 128;
    const int gidx = lane >> 2;
    const int tidx = lane & 3;

    const float* __restrict__ src_in = IN_IS_AGG ? (const float*)g_agg : in;
    const uint4* __restrict__ Wh4 =
        (const uint4*)(WSEL == 1 ? (const void*)g_W1h : (const void*)g_W2h);
    const uint4* __restrict__ Wl4 =
        (const uint4*)(WSEL == 1 ? (const void*)g_W1l : (const void*)g_W2l);

    if (RELU_BIAS) { if (tid < DH) bs[tid] = bias[tid]; }

    float acc[2][6][4];
#pragma unroll
    for (int mt = 0; mt < 2; mt++)
#pragma unroll
        for (int nt = 0; nt < 6; nt++)
#pragma unroll
            for (int q = 0; q < 4; q++) acc[mt][nt][q] = 0.0f;

    unsigned a_h0[2], a_l0[2];
#pragma unroll
    for (int mt = 0; mt < 2; mt++) {
        int row = wm * 32 + mt * 16 + (lane & 15);
        int col = (lane >> 4) * 8;
        a_h0[mt] = smem_u32(&Ah[0][row * 24 + col]);
        a_l0[mt] = smem_u32(&Al[0][row * 24 + col]);
    }
    unsigned b_h0[6], b_l0[6];
#pragma unroll
    for (int nt = 0; nt < 6; nt++) {
        int krow  = lane & 15;
        int cbase = wn * 48 + nt * 8;
        b_h0[nt] = smem_u32(&Bh[0][krow * 104 + cbase]);
        b_l0[nt] = smem_u32(&Bl[0][krow * 104 + cbase]);
    }
    const unsigned A_STRIDE = 128 * 24 * 2;
    const unsigned B_STRIDE = 16 * 104 * 2;

    // two in-flight register prefetch sets
    float4 pa[2][2];
    uint4  pb[2][2];

    auto load_stage = [&](int set, int k0) {
#pragma unroll
        for (int t = 0; t < 2; t++) {
            int idx = tid + t * 256;
            int row = idx >> 2, q = idx & 3;
            int gr = r0 + row, gk = k0 + q * 4;
            pa[set][t] = make_float4(0.f, 0.f, 0.f, 0.f);
            if (gr < NN && gk + 4 <= K)
                pa[set][t] = *reinterpret_cast<const float4*>(src_in + (size_t)gr * K + gk);
        }
#pragma unroll
        for (int t = 0; t < 2; t++) {
            int idx = tid + t * 256;
            if (idx < 384) {
                int half = (idx >= 192);
                int j  = idx - half * 192;
                int kk = j / 12, c = j % 12;
                int gk = k0 + kk;
                pb[set][t] = make_uint4(0u, 0u, 0u, 0u);
                if (gk < K)
                    pb[set][t] = (half ? Wl4 : Wh4)[gk * 12 + c];
            }
        }
    };

    auto store_stage = [&](int set, int buf, int k0) {
#pragma unroll
        for (int t = 0; t < 2; t++) {
            int idx = tid + t * 256;
            int row = idx >> 2, q = idx & 3;
            float e[4] = {pa[set][t].x, pa[set][t].y, pa[set][t].z, pa[set][t].w};
            unsigned hp[2], lp[2];
#pragma unroll
            for (int p = 0; p < 2; p++) {
                float f0 = e[p * 2], f1 = e[p * 2 + 1];
                if (RELU_BIAS) {
                    int gk = k0 + q * 4 + p * 2;
                    f0 = fmaxf(f0 + bs[gk], 0.0f);
                    f1 = fmaxf(f1 + bs[gk + 1], 0.0f);
                }
                __nv_bfloat162 h2 = make_bfloat162(__float2bfloat16(f0),
                                                   __float2bfloat16(f1));
                __nv_bfloat162 l2 = make_bfloat162(
                    __float2bfloat16(f0 - __bfloat162float(h2.x)),
                    __float2bfloat16(f1 - __bfloat162float(h2.y)));
                hp[p] = *reinterpret_cast<unsigned*>(&h2);
                lp[p] = *reinterpret_cast<unsigned*>(&l2);
            }
            *reinterpret_cast<uint2*>(&Ah[buf][row * 24 + q * 4]) = make_uint2(hp[0], hp[1]);
            *reinterpret_cast<uint2*>(&Al[buf][row * 24 + q * 4]) = make_uint2(lp[0], lp[1]);
        }
#pragma unroll
        for (int t = 0; t < 2; t++) {
            int idx = tid + t * 256;
            if (idx < 384) {
                int half = (idx >= 192);
                int j  = idx - half * 192;
                int kk = j / 12, c = j % 12;
                __nv_bfloat16* dstp = half ? Bl[buf] : Bh[buf];
                *reinterpret_cast<uint4*>(&dstp[kk * 104 + c * 8]) = pb[set][t];
            }
        }
    };

    const int nstage = (K + 15) / 16;        // >= 6 for both instantiations
    load_stage(0, 0);
    load_stage(1, 16);
    __syncthreads();                          // bs visible

    for (int s = 0; s < nstage; s++) {
        const int buf = s & 1;
        const int set = s & 1;
        store_stage(set, buf, s * 16);
        __syncthreads();
        if (s + 2 < nstage) load_stage(set, (s + 2) * 16);

        const unsigned ao = buf * A_STRIDE, bo = buf * B_STRIDE;
        unsigned ah[2][4], al[2][4], bh[6][2], bl[6][2];
#pragma unroll
        for (int mt = 0; mt < 2; mt++) {
            LDSM_X4(ah[mt], a_h0[mt] + ao);
            LDSM_X4(al[mt], a_l0[mt] + ao);
        }
#pragma unroll
        for (int nt = 0; nt < 6; nt++) {
            LDSM_X2_T(bh[nt], b_h0[nt] + bo);
            LDSM_X2_T(bl[nt], b_l0[nt] + bo);
        }
#pragma unroll
        for (int mt = 0; mt < 2; mt++)
#pragma unroll
            for (int nt = 0; nt < 6; nt++) {
                MMA_BF16(acc[mt][nt], ah[mt], bh[nt]);
                MMA_BF16(acc[mt][nt], ah[mt], bl[nt]);
                MMA_BF16(acc[mt][nt], al[mt], bh[nt]);
            }
    }

#pragma unroll
    for (int mt = 0; mt < 2; mt++) {
        int rbase = r0 + wm * 32 + mt * 16 + gidx;
#pragma unroll
        for (int half = 0; half < 2; half++) {
            int r = rbase + half * 8;
            if (r >= NN) continue;
            float ds = g_dis[r];
            float d2 = ds * ds;
#pragma unroll
            for (int nt = 0; nt < 6; nt++) {
                int c = wn * 48 + nt * 8 + tidx * 2;
                float v0 = acc[mt][nt][half * 2 + 0];
                float v1 = acc[mt][nt][half * 2 + 1];
                size_t o = (size_t)r * 96 + c;
                *reinterpret_cast<float2*>(g_h + o)   = make_float2(v0 * ds, v1 * ds);
                *reinterpret_cast<float2*>(g_agg + o) = make_float2(v0 * d2, v1 * d2);
            }
        }
    }
}

// ---------------- CSR scatter: one warp per dst node -------------------------
__global__ void __launch_bounds__(256)
k_scatter_csr()
{
    int w    = (blockIdx.x * 256 + threadIdx.x) >> 5;   // node id
    int lane = threadIdx.x & 31;
    if (w >= NN) return;
    const int beg = g_noff[w], end = g_noff[w + 1];

    float a0 = 0.f, a1 = 0.f, a2 = 0.f;
    int e = beg;
    for (; e + 4 <= end; e += 4) {
        unsigned s0 = g_esrc[e],     s1 = g_esrc[e + 1];
        unsigned s2 = g_esrc[e + 2], s3 = g_esrc[e + 3];
        const float* r0 = g_h + (size_t)s0 * 96;
        const float* r1 = g_h + (size_t)s1 * 96;
        const float* r2 = g_h + (size_t)s2 * 96;
        const float* r3 = g_h + (size_t)s3 * 96;
        float v00 = r0[lane], v01 = r0[lane + 32], v02 = r0[lane + 64];
        float v10 = r1[lane], v11 = r1[lane + 32], v12 = r1[lane + 64];
        float v20 = r2[lane], v21 = r2[lane + 32], v22 = r2[lane + 64];
        float v30 = r3[lane], v31 = r3[lane + 32], v32 = r3[lane + 64];
        a0 += (v00 + v10) + (v20 + v30);
        a1 += (v01 + v11) + (v21 + v31);
        a2 += (v02 + v12) + (v22 + v32);
    }
    for (; e < end; e++) {
        const float* r = g_h + (size_t)g_esrc[e] * 96;
        a0 += r[lane]; a1 += r[lane + 32]; a2 += r[lane + 64];
    }
    float dw = g_dis[w];
    float* o = g_agg + (size_t)w * 96;
    o[lane]      += a0 * dw;
    o[lane + 32] += a1 * dw;
    o[lane + 64] += a2 * dw;
}

// ---------------- pooling ----------------------------------------------------
__global__ void __launch_bounds__(96)
k_pool(const float* __restrict__ b2, const int* __restrict__ batch)
{
    int c  = threadIdx.x;
    int r0 = blockIdx.x * 64;
    int re = min(r0 + 64, NN);
    if (r0 >= NN) return;
    float bb = b2[c];
    float acc = 0.0f;
    int cur = batch[r0];
    int run = 0;
    for (int r = r0; r < re; r++) {
        int g = batch[r];
        if (g != cur) {
            atomicAdd(&g_pool[cur * DH + c], acc);
            if (c == 0) atomicAdd(&g_cnt[cur], (float)run);
            acc = 0.0f; run = 0; cur = g;
        }
        acc += fmaxf(g_agg[(size_t)r * 96 + c] + bb, 0.0f);
        run++;
    }
    atomicAdd(&g_pool[cur * DH + c], acc);
    if (c == 0) atomicAdd(&g_cnt[cur], (float)run);
}

// ---------------- head -------------------------------------------------------
__global__ void k_fc(const float* __restrict__ Wfc, const float* __restrict__ bfc,
                     float* __restrict__ out)
{
    int t = threadIdx.x;
    if (t >= GG * DOUT) return;
    int g = t >> 1, o = t & 1;
    float cn = fmaxf(g_cnt[g], 1.0f);
    float s = bfc[o];
    for (int c = 0; c < DH; c++)
        s += (g_pool[g * DH + c] / cn) * Wfc[c * DOUT + o];
    out[g * DOUT + o] = s;
}

// ---------------- launch ------------------------------------------------------
extern "C" void kernel_launch(void* const* d_in, const int* in_sizes, int n_in,
                              void* d_out, int out_size)
{
    const float* x    = (const float*)d_in[0];
    const float* W1   = (const float*)d_in[1];
    const float* b1   = (const float*)d_in[2];
    const float* W2   = (const float*)d_in[3];
    const float* b2   = (const float*)d_in[4];
    const float* Wfc  = (const float*)d_in[5];
    const float* bfc  = (const float*)d_in[6];
    const int*   src  = (const int*)d_in[7];
    const int*   dst  = (const int*)d_in[8];
    const int*   batch= (const int*)d_in[9];
    float* out = (float*)d_out;

    const int nb_n = (NN + 255) / 256;
    const int nb_e = (EE + 255) / 256;
    const int nb_g = (NN + 127) / 128;
    const int nb_p = (NN + 63) / 64;
    const int nb_s = (NN * 32 + 255) / 256;   // one warp per node

    k_wsplit   <<<nb_n, 256>>>(W1, W2);       // + ncnt/pool/cnt init
    k_deg_count<<<nb_e, 256>>>(dst);
    k_scanA    <<<SCB, 256>>>();
    k_scanC    <<<SCB, 256>>>();              // + dis = rsqrt(1+cnt)
    k_reorder  <<<nb_e, 256>>>(src, dst);

    // layer 1
    k_gemm<DIN, false, false, 1><<<nb_g, 256>>>(x, b1);
    k_scatter_csr<<<nb_s, 256>>>();

    // layer 2
    k_gemm<DH, true, true, 2><<<nb_g, 256>>>(nullptr, b1);
    k_scatter_csr<<<nb_s, 256>>>();

    k_pool<<<nb_p, 96>>>(b2, batch);
    k_fc  <<<1, 128>>>(Wfc, bfc, out);
}

// round 10
// speedup vs baseline: 1.0322x; 1.0322x over previous
#include <cuda_runtime.h>
#include <cuda_bf16.h>
#include <math.h>

#define NN    50000
#define EE    800000
#define DIN   300
#define DH    96
#define DOUT  2
#define GG    64
#define SCB   196                    // scan blocks: ceil(50000/256)

// ---------------- scratch (device globals; no allocation allowed) -----------
__device__ float g_dis[NN];
__device__ float g_h  [(size_t)NN * DH];    // h * dis (pre-scaled!)
__device__ float g_agg[(size_t)NN * DH];
__device__ float g_pool[GG * DH];
__device__ float g_cnt [GG];
__device__ __nv_bfloat16 g_W1h[DIN * DH], g_W1l[DIN * DH];
__device__ __nv_bfloat16 g_W2h[DH * DH],  g_W2l[DH * DH];
// CSR scratch
__device__ int      g_ncnt[NN];
__device__ int      g_tmp [NN];
__device__ int      g_bsum[256];
__device__ int      g_noff[NN + 1];
__device__ int      g_ncur[NN];
__device__ unsigned g_esrc[EE];      // src ids sorted by dst

// ---------------- weight split + init ---------------------------------------
__global__ void k_wsplit(const float* __restrict__ W1, const float* __restrict__ W2) {
    int i = blockIdx.x * blockDim.x + threadIdx.x;
    if (i < DIN * DH) {
        float f = W1[i];
        __nv_bfloat16 hi = __float2bfloat16(f);
        g_W1h[i] = hi;
        g_W1l[i] = __float2bfloat16(f - __bfloat162float(hi));
    }
    if (i < DH * DH) {
        float f = W2[i];
        __nv_bfloat16 hi = __float2bfloat16(f);
        g_W2h[i] = hi;
        g_W2l[i] = __float2bfloat16(f - __bfloat162float(hi));
    }
    if (i < NN) g_ncnt[i] = 0;
    if (i < GG * DH) g_pool[i] = 0.0f;
    if (i < GG)      g_cnt[i]  = 0.0f;
}
__global__ void k_deg_count(const int* __restrict__ dst) {
    int e = blockIdx.x * blockDim.x + threadIdx.x;
    if (e < EE) atomicAdd(&g_ncnt[dst[e]], 1);
}

// ---------------- scan (dis + graph node counts fused into C) ----------------
__global__ void __launch_bounds__(256) k_scanA() {
    __shared__ int sh[256];
    int t  = threadIdx.x;
    int gi = blockIdx.x * 256 + t;
    int v  = (gi < NN) ? g_ncnt[gi] : 0;
    sh[t] = v; __syncthreads();
#pragma unroll
    for (int off = 1; off < 256; off <<= 1) {
        int u = (t >= off) ? sh[t - off] : 0;
        __syncthreads();
        sh[t] += u;
        __syncthreads();
    }
    if (gi < NN) g_tmp[gi] = sh[t];                   // inclusive within block
    if (t == 255) g_bsum[blockIdx.x] = sh[255];
}
__global__ void __launch_bounds__(256) k_scanC(const int* __restrict__ batch) {
    __shared__ int sb[256];
    int t = threadIdx.x;
    sb[t] = (t < SCB) ? g_bsum[t] : 0;
    __syncthreads();
#pragma unroll
    for (int off = 1; off < 256; off <<= 1) {
        int u = (t >= off) ? sb[t - off] : 0;
        __syncthreads();
        sb[t] += u;
        __syncthreads();
    }
    int gi = blockIdx.x * 256 + t;
    if (gi >= NN) return;
    int base = (blockIdx.x > 0) ? sb[blockIdx.x - 1] : 0;
    int cnt  = g_ncnt[gi];
    int inc  = g_tmp[gi] + base;
    g_noff[gi + 1] = inc;
    g_ncur[gi]     = inc - cnt;
    g_dis[gi]      = rsqrtf(1.0f + (float)cnt);       // fused deg_finish
    atomicAdd(&g_cnt[batch[gi]], 1.0f);               // fused pool counts
    if (gi == 0) g_noff[0] = 0;
}
__global__ void __launch_bounds__(256)
k_reorder(const int* __restrict__ src, const int* __restrict__ dst) {
    int e = blockIdx.x * blockDim.x + threadIdx.x;
    if (e >= EE) return;
    int pos = atomicAdd(&g_ncur[dst[e]], 1);
    g_esrc[pos] = (unsigned)src[e];
}

// ---------------- mma helpers ------------------------------------------------
__device__ __forceinline__ unsigned smem_u32(const void* p) {
    return (unsigned)__cvta_generic_to_shared(p);
}
#define LDSM_X4(r, addr) \
    asm volatile("ldmatrix.sync.aligned.m8n8.x4.shared.b16 {%0,%1,%2,%3},[%4];" \
                 : "=r"((r)[0]), "=r"((r)[1]), "=r"((r)[2]), "=r"((r)[3]) : "r"(addr))
#define LDSM_X2_T(r, addr) \
    asm volatile("ldmatrix.sync.aligned.m8n8.x2.trans.shared.b16 {%0,%1},[%2];" \
                 : "=r"((r)[0]), "=r"((r)[1]) : "r"(addr))
#define MMA_BF16(d, a, b) \
    asm volatile("mma.sync.aligned.m16n8k16.row.col.f32.bf16.bf16.f32 " \
                 "{%0,%1,%2,%3},{%4,%5,%6,%7},{%8,%9},{%0,%1,%2,%3};" \
                 : "+f"((d)[0]), "+f"((d)[1]), "+f"((d)[2]), "+f"((d)[3]) \
                 : "r"((a)[0]), "r"((a)[1]), "r"((a)[2]), "r"((a)[3]), \
                   "r"((b)[0]), "r"((b)[1]))

// ---------------- pipelined bf16-split tensor GEMM: out = in @ W ------------
// (R8-proven form: single-stage register prefetch, double-buffered smem.)
// Epilogue: g_h = acc * dis (pre-scaled for scatter); g_agg = acc * dis^2.
template <int K, bool RELU_BIAS, bool IN_IS_AGG, int WSEL>
__global__ void __launch_bounds__(256, 2)
k_gemm(const float* __restrict__ in, const float* __restrict__ bias)
{
    __shared__ __nv_bfloat16 Ah[2][128 * 24], Al[2][128 * 24];
    __shared__ __nv_bfloat16 Bh[2][16 * 104], Bl[2][16 * 104];
    __shared__ float bs[DH];

    const int tid  = threadIdx.x;
    const int lane = tid & 31;
    const int wid  = tid >> 5;
    const int wm   = wid & 3;
    const int wn   = wid >> 2;
    const int r0   = blockIdx.x * 128;
    const int gidx = lane >> 2;
    const int tidx = lane & 3;

    const float* __restrict__ src_in = IN_IS_AGG ? (const float*)g_agg : in;
    const uint4* __restrict__ Wh4 =
        (const uint4*)(WSEL == 1 ? (const void*)g_W1h : (const void*)g_W2h);
    const uint4* __restrict__ Wl4 =
        (const uint4*)(WSEL == 1 ? (const void*)g_W1l : (const void*)g_W2l);

    if (RELU_BIAS) { if (tid < DH) bs[tid] = bias[tid]; }

    float acc[2][6][4];
#pragma unroll
    for (int mt = 0; mt < 2; mt++)
#pragma unroll
        for (int nt = 0; nt < 6; nt++)
#pragma unroll
            for (int q = 0; q < 4; q++) acc[mt][nt][q] = 0.0f;

    unsigned a_h0[2], a_l0[2];
#pragma unroll
    for (int mt = 0; mt < 2; mt++) {
        int row = wm * 32 + mt * 16 + (lane & 15);
        int col = (lane >> 4) * 8;
        a_h0[mt] = smem_u32(&Ah[0][row * 24 + col]);
        a_l0[mt] = smem_u32(&Al[0][row * 24 + col]);
    }
    unsigned b_h0[6], b_l0[6];
#pragma unroll
    for (int nt = 0; nt < 6; nt++) {
        int krow  = lane & 15;
        int cbase = wn * 48 + nt * 8;
        b_h0[nt] = smem_u32(&Bh[0][krow * 104 + cbase]);
        b_l0[nt] = smem_u32(&Bl[0][krow * 104 + cbase]);
    }
    const unsigned A_STRIDE = 128 * 24 * 2;
    const unsigned B_STRIDE = 16 * 104 * 2;

    float4 pa[2];
    uint4  pb[2];

    auto load_stage = [&](int k0) {
#pragma unroll
        for (int t = 0; t < 2; t++) {
            int idx = tid + t * 256;
            int row = idx >> 2, q = idx & 3;
            int gr = r0 + row, gk = k0 + q * 4;
            pa[t] = make_float4(0.f, 0.f, 0.f, 0.f);
            if (gr < NN && gk + 4 <= K)
                pa[t] = *reinterpret_cast<const float4*>(src_in + (size_t)gr * K + gk);
        }
#pragma unroll
        for (int t = 0; t < 2; t++) {
            int idx = tid + t * 256;
            if (idx < 384) {
                int half = (idx >= 192);
                int j  = idx - half * 192;
                int kk = j / 12, c = j % 12;
                int gk = k0 + kk;
                pb[t] = make_uint4(0u, 0u, 0u, 0u);
                if (gk < K)
                    pb[t] = (half ? Wl4 : Wh4)[gk * 12 + c];
            }
        }
    };

    auto store_stage = [&](int buf, int k0) {
#pragma unroll
        for (int t = 0; t < 2; t++) {
            int idx = tid + t * 256;
            int row = idx >> 2, q = idx & 3;
            float e[4] = {pa[t].x, pa[t].y, pa[t].z, pa[t].w};
            unsigned hp[2], lp[2];
#pragma unroll
            for (int p = 0; p < 2; p++) {
                float f0 = e[p * 2], f1 = e[p * 2 + 1];
                if (RELU_BIAS) {
                    int gk = k0 + q * 4 + p * 2;
                    f0 = fmaxf(f0 + bs[gk], 0.0f);
                    f1 = fmaxf(f1 + bs[gk + 1], 0.0f);
                }
                __nv_bfloat162 h2 = make_bfloat162(__float2bfloat16(f0),
                                                   __float2bfloat16(f1));
                __nv_bfloat162 l2 = make_bfloat162(
                    __float2bfloat16(f0 - __bfloat162float(h2.x)),
                    __float2bfloat16(f1 - __bfloat162float(h2.y)));
                hp[p] = *reinterpret_cast<unsigned*>(&h2);
                lp[p] = *reinterpret_cast<unsigned*>(&l2);
            }
            *reinterpret_cast<uint2*>(&Ah[buf][row * 24 + q * 4]) = make_uint2(hp[0], hp[1]);
            *reinterpret_cast<uint2*>(&Al[buf][row * 24 + q * 4]) = make_uint2(lp[0], lp[1]);
        }
#pragma unroll
        for (int t = 0; t < 2; t++) {
            int idx = tid + t * 256;
            if (idx < 384) {
                int half = (idx >= 192);
                int j  = idx - half * 192;
                int kk = j / 12, c = j % 12;
                __nv_bfloat16* dstp = half ? Bl[buf] : Bh[buf];
                *reinterpret_cast<uint4*>(&dstp[kk * 104 + c * 8]) = pb[t];
            }
        }
    };

    const int nstage = (K + 15) / 16;
    load_stage(0);
    __syncthreads();

    for (int s = 0; s < nstage; s++) {
        const int buf = s & 1;
        store_stage(buf, s * 16);
        __syncthreads();
        if (s + 1 < nstage) load_stage((s + 1) * 16);

        const unsigned ao = buf * A_STRIDE, bo = buf * B_STRIDE;
        unsigned ah[2][4], al[2][4], bh[6][2], bl[6][2];
#pragma unroll
        for (int mt = 0; mt < 2; mt++) {
            LDSM_X4(ah[mt], a_h0[mt] + ao);
            LDSM_X4(al[mt], a_l0[mt] + ao);
        }
#pragma unroll
        for (int nt = 0; nt < 6; nt++) {
            LDSM_X2_T(bh[nt], b_h0[nt] + bo);
            LDSM_X2_T(bl[nt], b_l0[nt] + bo);
        }
#pragma unroll
        for (int mt = 0; mt < 2; mt++)
#pragma unroll
            for (int nt = 0; nt < 6; nt++) {
                MMA_BF16(acc[mt][nt], ah[mt], bh[nt]);
                MMA_BF16(acc[mt][nt], ah[mt], bl[nt]);
                MMA_BF16(acc[mt][nt], al[mt], bh[nt]);
            }
    }

#pragma unroll
    for (int mt = 0; mt < 2; mt++) {
        int rbase = r0 + wm * 32 + mt * 16 + gidx;
#pragma unroll
        for (int half = 0; half < 2; half++) {
            int r = rbase + half * 8;
            if (r >= NN) continue;
            float ds = g_dis[r];
            float d2 = ds * ds;
#pragma unroll
            for (int nt = 0; nt < 6; nt++) {
                int c = wn * 48 + nt * 8 + tidx * 2;
                float v0 = acc[mt][nt][half * 2 + 0];
                float v1 = acc[mt][nt][half * 2 + 1];
                size_t o = (size_t)r * 96 + c;
                *reinterpret_cast<float2*>(g_h + o)   = make_float2(v0 * ds, v1 * ds);
                *reinterpret_cast<float2*>(g_agg + o) = make_float2(v0 * d2, v1 * d2);
            }
        }
    }
}

// ---------------- CSR scatter: one warp per dst node -------------------------
// FINAL=false: g_agg[w] += sum * dis[w]  (layer 1)
// FINAL=true : pool[batch[w]] += relu(g_agg[w] + sum*dis[w] + b2)  (layer 2,
//              pooling fused; g_agg not written)
template <bool FINAL>
__global__ void __launch_bounds__(256)
k_scatter_csr(const float* __restrict__ b2, const int* __restrict__ batch)
{
    int w    = (blockIdx.x * 256 + threadIdx.x) >> 5;   // node id
    int lane = threadIdx.x & 31;
    if (w >= NN) return;
    const int beg = g_noff[w], end = g_noff[w + 1];

    float a0 = 0.f, a1 = 0.f, a2 = 0.f;
    int e = beg;
    for (; e + 4 <= end; e += 4) {
        unsigned s0 = g_esrc[e],     s1 = g_esrc[e + 1];
        unsigned s2 = g_esrc[e + 2], s3 = g_esrc[e + 3];
        const float* r0 = g_h + (size_t)s0 * 96;
        const float* r1 = g_h + (size_t)s1 * 96;
        const float* r2 = g_h + (size_t)s2 * 96;
        const float* r3 = g_h + (size_t)s3 * 96;
        float v00 = r0[lane], v01 = r0[lane + 32], v02 = r0[lane + 64];
        float v10 = r1[lane], v11 = r1[lane + 32], v12 = r1[lane + 64];
        float v20 = r2[lane], v21 = r2[lane + 32], v22 = r2[lane + 64];
        float v30 = r3[lane], v31 = r3[lane + 32], v32 = r3[lane + 64];
        a0 += (v00 + v10) + (v20 + v30);
        a1 += (v01 + v11) + (v21 + v31);
        a2 += (v02 + v12) + (v22 + v32);
    }
    for (; e < end; e++) {
        const float* r = g_h + (size_t)g_esrc[e] * 96;
        a0 += r[lane]; a1 += r[lane + 32]; a2 += r[lane + 64];
    }
    float dw = g_dis[w];
    float* o = g_agg + (size_t)w * 96;
    if (!FINAL) {
        o[lane]      += a0 * dw;
        o[lane + 32] += a1 * dw;
        o[lane + 64] += a2 * dw;
    } else {
        float p0 = fmaxf(o[lane]      + a0 * dw + b2[lane],      0.0f);
        float p1 = fmaxf(o[lane + 32] + a1 * dw + b2[lane + 32], 0.0f);
        float p2 = fmaxf(o[lane + 64] + a2 * dw + b2[lane + 64], 0.0f);
        float* pl = g_pool + batch[w] * DH;
        atomicAdd(pl + lane,      p0);
        atomicAdd(pl + lane + 32, p1);
        atomicAdd(pl + lane + 64, p2);
    }
}

// ---------------- head -------------------------------------------------------
__global__ void k_fc(const float* __restrict__ Wfc, const float* __restrict__ bfc,
                     float* __restrict__ out)
{
    int t = threadIdx.x;
    if (t >= GG * DOUT) return;
    int g = t >> 1, o = t & 1;
    float cn = fmaxf(g_cnt[g], 1.0f);
    float s = bfc[o];
    for (int c = 0; c < DH; c++)
        s += (g_pool[g * DH + c] / cn) * Wfc[c * DOUT + o];
    out[g * DOUT + o] = s;
}

// ---------------- launch ------------------------------------------------------
extern "C" void kernel_launch(void* const* d_in, const int* in_sizes, int n_in,
                              void* d_out, int out_size)
{
    const float* x    = (const float*)d_in[0];
    const float* W1   = (const float*)d_in[1];
    const float* b1   = (const float*)d_in[2];
    const float* W2   = (const float*)d_in[3];
    const float* b2   = (const float*)d_in[4];
    const float* Wfc  = (const float*)d_in[5];
    const float* bfc  = (const float*)d_in[6];
    const int*   src  = (const int*)d_in[7];
    const int*   dst  = (const int*)d_in[8];
    const int*   batch= (const int*)d_in[9];
    float* out = (float*)d_out;

    const int nb_n = (NN + 255) / 256;
    const int nb_e = (EE + 255) / 256;
    const int nb_g = (NN + 127) / 128;
    const int nb_s = (NN * 32 + 255) / 256;   // one warp per node

    k_wsplit   <<<nb_n, 256>>>(W1, W2);       // + ncnt/pool/cnt init
    k_deg_count<<<nb_e, 256>>>(dst);
    k_scanA    <<<SCB, 256>>>();
    k_scanC    <<<SCB, 256>>>(batch);         // + dis + pool counts
    k_reorder  <<<nb_e, 256>>>(src, dst);

    // layer 1
    k_gemm<DIN, false, false, 1><<<nb_g, 256>>>(x, b1);
    k_scatter_csr<false><<<nb_s, 256>>>(b2, batch);

    // layer 2 (scatter fused with relu+bias+pool)
    k_gemm<DH, true, true, 2><<<nb_g, 256>>>(nullptr, b1);
    k_scatter_csr<true><<<nb_s, 256>>>(b2, batch);

    k_fc<<<1, 128>>>(Wfc, bfc, out);
}

// round 11
// speedup vs baseline: 1.2032x; 1.1657x over previous
#include <cuda_runtime.h>
#include <cuda_bf16.h>
#include <math.h>

#define NN    50000
#define EE    800000
#define DIN   300
#define DH    96
#define DOUT  2
#define GG    64
#define SCB   196                    // scan blocks: ceil(50000/256)

// ---------------- scratch (device globals; no allocation allowed) -----------
__device__ float g_dis[NN];
__device__ float g_h  [(size_t)NN * DH];    // h * dis (pre-scaled!)
__device__ float g_agg[(size_t)NN * DH];
__device__ float g_pool[GG * DH];
__device__ __nv_bfloat16 g_W1h[DIN * DH], g_W1l[DIN * DH];
__device__ __nv_bfloat16 g_W2h[DH * DH],  g_W2l[DH * DH];
// CSR scratch
__device__ int      g_ncnt[NN];
__device__ int      g_tmp [NN];
__device__ int      g_bsum[256];
__device__ int      g_noff[NN + 1];
__device__ int      g_ncur[NN];
__device__ unsigned g_esrc[EE];      // src ids sorted by dst

// ---------------- weight split + init ---------------------------------------
__global__ void k_wsplit(const float* __restrict__ W1, const float* __restrict__ W2) {
    int i = blockIdx.x * blockDim.x + threadIdx.x;
    if (i < DIN * DH) {
        float f = W1[i];
        __nv_bfloat16 hi = __float2bfloat16(f);
        g_W1h[i] = hi;
        g_W1l[i] = __float2bfloat16(f - __bfloat162float(hi));
    }
    if (i < DH * DH) {
        float f = W2[i];
        __nv_bfloat16 hi = __float2bfloat16(f);
        g_W2h[i] = hi;
        g_W2l[i] = __float2bfloat16(f - __bfloat162float(hi));
    }
    if (i < NN) g_ncnt[i] = 0;
    if (i < GG * DH) g_pool[i] = 0.0f;
}
__global__ void k_deg_count(const int* __restrict__ dst) {
    int e = blockIdx.x * blockDim.x + threadIdx.x;
    if (e < EE) atomicAdd(&g_ncnt[dst[e]], 1);
}

// ---------------- scan (dis fused into C; NO pool-count atomics) -------------
__global__ void __launch_bounds__(256) k_scanA() {
    __shared__ int sh[256];
    int t  = threadIdx.x;
    int gi = blockIdx.x * 256 + t;
    int v  = (gi < NN) ? g_ncnt[gi] : 0;
    sh[t] = v; __syncthreads();
#pragma unroll
    for (int off = 1; off < 256; off <<= 1) {
        int u = (t >= off) ? sh[t - off] : 0;
        __syncthreads();
        sh[t] += u;
        __syncthreads();
    }
    if (gi < NN) g_tmp[gi] = sh[t];                   // inclusive within block
    if (t == 255) g_bsum[blockIdx.x] = sh[255];
}
__global__ void __launch_bounds__(256) k_scanC() {
    __shared__ int sb[256];
    int t = threadIdx.x;
    sb[t] = (t < SCB) ? g_bsum[t] : 0;
    __syncthreads();
#pragma unroll
    for (int off = 1; off < 256; off <<= 1) {
        int u = (t >= off) ? sb[t - off] : 0;
        __syncthreads();
        sb[t] += u;
        __syncthreads();
    }
    int gi = blockIdx.x * 256 + t;
    if (gi >= NN) return;
    int base = (blockIdx.x > 0) ? sb[blockIdx.x - 1] : 0;
    int cnt  = g_ncnt[gi];
    int inc  = g_tmp[gi] + base;
    g_noff[gi + 1] = inc;
    g_ncur[gi]     = inc - cnt;
    g_dis[gi]      = rsqrtf(1.0f + (float)cnt);       // fused deg_finish
    if (gi == 0) g_noff[0] = 0;
}
__global__ void __launch_bounds__(256)
k_reorder(const int* __restrict__ src, const int* __restrict__ dst) {
    int e = blockIdx.x * blockDim.x + threadIdx.x;
    if (e >= EE) return;
    int pos = atomicAdd(&g_ncur[dst[e]], 1);
    g_esrc[pos] = (unsigned)src[e];
}

// ---------------- mma helpers ------------------------------------------------
__device__ __forceinline__ unsigned smem_u32(const void* p) {
    return (unsigned)__cvta_generic_to_shared(p);
}
#define LDSM_X4(r, addr) \
    asm volatile("ldmatrix.sync.aligned.m8n8.x4.shared.b16 {%0,%1,%2,%3},[%4];" \
                 : "=r"((r)[0]), "=r"((r)[1]), "=r"((r)[2]), "=r"((r)[3]) : "r"(addr))
#define LDSM_X2_T(r, addr) \
    asm volatile("ldmatrix.sync.aligned.m8n8.x2.trans.shared.b16 {%0,%1},[%2];" \
                 : "=r"((r)[0]), "=r"((r)[1]) : "r"(addr))
#define MMA_BF16(d, a, b) \
    asm volatile("mma.sync.aligned.m16n8k16.row.col.f32.bf16.bf16.f32 " \
                 "{%0,%1,%2,%3},{%4,%5,%6,%7},{%8,%9},{%0,%1,%2,%3};" \
                 : "+f"((d)[0]), "+f"((d)[1]), "+f"((d)[2]), "+f"((d)[3]) \
                 : "r"((a)[0]), "r"((a)[1]), "r"((a)[2]), "r"((a)[3]), \
                   "r"((b)[0]), "r"((b)[1]))

// ---------------- pipelined bf16-split tensor GEMM: out = in @ W ------------
// (R8-proven form.) Epilogue: g_h = acc*dis; g_agg = acc*dis^2.
template <int K, bool RELU_BIAS, bool IN_IS_AGG, int WSEL>
__global__ void __launch_bounds__(256, 2)
k_gemm(const float* __restrict__ in, const float* __restrict__ bias)
{
    __shared__ __nv_bfloat16 Ah[2][128 * 24], Al[2][128 * 24];
    __shared__ __nv_bfloat16 Bh[2][16 * 104], Bl[2][16 * 104];
    __shared__ float bs[DH];

    const int tid  = threadIdx.x;
    const int lane = tid & 31;
    const int wid  = tid >> 5;
    const int wm   = wid & 3;
    const int wn   = wid >> 2;
    const int r0   = blockIdx.x * 128;
    const int gidx = lane >> 2;
    const int tidx = lane & 3;

    const float* __restrict__ src_in = IN_IS_AGG ? (const float*)g_agg : in;
    const uint4* __restrict__ Wh4 =
        (const uint4*)(WSEL == 1 ? (const void*)g_W1h : (const void*)g_W2h);
    const uint4* __restrict__ Wl4 =
        (const uint4*)(WSEL == 1 ? (const void*)g_W1l : (const void*)g_W2l);

    if (RELU_BIAS) { if (tid < DH) bs[tid] = bias[tid]; }

    float acc[2][6][4];
#pragma unroll
    for (int mt = 0; mt < 2; mt++)
#pragma unroll
        for (int nt = 0; nt < 6; nt++)
#pragma unroll
            for (int q = 0; q < 4; q++) acc[mt][nt][q] = 0.0f;

    unsigned a_h0[2], a_l0[2];
#pragma unroll
    for (int mt = 0; mt < 2; mt++) {
        int row = wm * 32 + mt * 16 + (lane & 15);
        int col = (lane >> 4) * 8;
        a_h0[mt] = smem_u32(&Ah[0][row * 24 + col]);
        a_l0[mt] = smem_u32(&Al[0][row * 24 + col]);
    }
    unsigned b_h0[6], b_l0[6];
#pragma unroll
    for (int nt = 0; nt < 6; nt++) {
        int krow  = lane & 15;
        int cbase = wn * 48 + nt * 8;
        b_h0[nt] = smem_u32(&Bh[0][krow * 104 + cbase]);
        b_l0[nt] = smem_u32(&Bl[0][krow * 104 + cbase]);
    }
    const unsigned A_STRIDE = 128 * 24 * 2;
    const unsigned B_STRIDE = 16 * 104 * 2;

    float4 pa[2];
    uint4  pb[2];

    auto load_stage = [&](int k0) {
#pragma unroll
        for (int t = 0; t < 2; t++) {
            int idx = tid + t * 256;
            int row = idx >> 2, q = idx & 3;
            int gr = r0 + row, gk = k0 + q * 4;
            pa[t] = make_float4(0.f, 0.f, 0.f, 0.f);
            if (gr < NN && gk + 4 <= K)
                pa[t] = *reinterpret_cast<const float4*>(src_in + (size_t)gr * K + gk);
        }
#pragma unroll
        for (int t = 0; t < 2; t++) {
            int idx = tid + t * 256;
            if (idx < 384) {
                int half = (idx >= 192);
                int j  = idx - half * 192;
                int kk = j / 12, c = j % 12;
                int gk = k0 + kk;
                pb[t] = make_uint4(0u, 0u, 0u, 0u);
                if (gk < K)
                    pb[t] = (half ? Wl4 : Wh4)[gk * 12 + c];
            }
        }
    };

    auto store_stage = [&](int buf, int k0) {
#pragma unroll
        for (int t = 0; t < 2; t++) {
            int idx = tid + t * 256;
            int row = idx >> 2, q = idx & 3;
            float e[4] = {pa[t].x, pa[t].y, pa[t].z, pa[t].w};
            unsigned hp[2], lp[2];
#pragma unroll
            for (int p = 0; p < 2; p++) {
                float f0 = e[p * 2], f1 = e[p * 2 + 1];
                if (RELU_BIAS) {
                    int gk = k0 + q * 4 + p * 2;
                    f0 = fmaxf(f0 + bs[gk], 0.0f);
                    f1 = fmaxf(f1 + bs[gk + 1], 0.0f);
                }
                __nv_bfloat162 h2 = make_bfloat162(__float2bfloat16(f0),
                                                   __float2bfloat16(f1));
                __nv_bfloat162 l2 = make_bfloat162(
                    __float2bfloat16(f0 - __bfloat162float(h2.x)),
                    __float2bfloat16(f1 - __bfloat162float(h2.y)));
                hp[p] = *reinterpret_cast<unsigned*>(&h2);
                lp[p] = *reinterpret_cast<unsigned*>(&l2);
            }
            *reinterpret_cast<uint2*>(&Ah[buf][row * 24 + q * 4]) = make_uint2(hp[0], hp[1]);
            *reinterpret_cast<uint2*>(&Al[buf][row * 24 + q * 4]) = make_uint2(lp[0], lp[1]);
        }
#pragma unroll
        for (int t = 0; t < 2; t++) {
            int idx = tid + t * 256;
            if (idx < 384) {
                int half = (idx >= 192);
                int j  = idx - half * 192;
                int kk = j / 12, c = j % 12;
                __nv_bfloat16* dstp = half ? Bl[buf] : Bh[buf];
                *reinterpret_cast<uint4*>(&dstp[kk * 104 + c * 8]) = pb[t];
            }
        }
    };

    const int nstage = (K + 15) / 16;
    load_stage(0);
    __syncthreads();

    for (int s = 0; s < nstage; s++) {
        const int buf = s & 1;
        store_stage(buf, s * 16);
        __syncthreads();
        if (s + 1 < nstage) load_stage((s + 1) * 16);

        const unsigned ao = buf * A_STRIDE, bo = buf * B_STRIDE;
        unsigned ah[2][4], al[2][4], bh[6][2], bl[6][2];
#pragma unroll
        for (int mt = 0; mt < 2; mt++) {
            LDSM_X4(ah[mt], a_h0[mt] + ao);
            LDSM_X4(al[mt], a_l0[mt] + ao);
        }
#pragma unroll
        for (int nt = 0; nt < 6; nt++) {
            LDSM_X2_T(bh[nt], b_h0[nt] + bo);
            LDSM_X2_T(bl[nt], b_l0[nt] + bo);
        }
#pragma unroll
        for (int mt = 0; mt < 2; mt++)
#pragma unroll
            for (int nt = 0; nt < 6; nt++) {
                MMA_BF16(acc[mt][nt], ah[mt], bh[nt]);
                MMA_BF16(acc[mt][nt], ah[mt], bl[nt]);
                MMA_BF16(acc[mt][nt], al[mt], bh[nt]);
            }
    }

#pragma unroll
    for (int mt = 0; mt < 2; mt++) {
        int rbase = r0 + wm * 32 + mt * 16 + gidx;
#pragma unroll
        for (int half = 0; half < 2; half++) {
            int r = rbase + half * 8;
            if (r >= NN) continue;
            float ds = g_dis[r];
            float d2 = ds * ds;
#pragma unroll
            for (int nt = 0; nt < 6; nt++) {
                int c = wn * 48 + nt * 8 + tidx * 2;
                float v0 = acc[mt][nt][half * 2 + 0];
                float v1 = acc[mt][nt][half * 2 + 1];
                size_t o = (size_t)r * 96 + c;
                *reinterpret_cast<float2*>(g_h + o)   = make_float2(v0 * ds, v1 * ds);
                *reinterpret_cast<float2*>(g_agg + o) = make_float2(v0 * d2, v1 * d2);
            }
        }
    }
}

// ---------------- CSR scatter: one warp per dst node -------------------------
// FINAL=false: g_agg[w] += sum * dis[w]  (layer 1)
// FINAL=true : pool[batch[w]] += relu(g_agg[w] + sum*dis[w] + b2)  (layer 2,
//              pooling fused; g_agg not written)
template <bool FINAL>
__global__ void __launch_bounds__(256)
k_scatter_csr(const float* __restrict__ b2, const int* __restrict__ batch)
{
    int w    = (blockIdx.x * 256 + threadIdx.x) >> 5;   // node id
    int lane = threadIdx.x & 31;
    if (w >= NN) return;
    const int beg = g_noff[w], end = g_noff[w + 1];

    float a0 = 0.f, a1 = 0.f, a2 = 0.f;
    int e = beg;
    for (; e + 4 <= end; e += 4) {
        unsigned s0 = g_esrc[e],     s1 = g_esrc[e + 1];
        unsigned s2 = g_esrc[e + 2], s3 = g_esrc[e + 3];
        const float* r0 = g_h + (size_t)s0 * 96;
        const float* r1 = g_h + (size_t)s1 * 96;
        const float* r2 = g_h + (size_t)s2 * 96;
        const float* r3 = g_h + (size_t)s3 * 96;
        float v00 = r0[lane], v01 = r0[lane + 32], v02 = r0[lane + 64];
        float v10 = r1[lane], v11 = r1[lane + 32], v12 = r1[lane + 64];
        float v20 = r2[lane], v21 = r2[lane + 32], v22 = r2[lane + 64];
        float v30 = r3[lane], v31 = r3[lane + 32], v32 = r3[lane + 64];
        a0 += (v00 + v10) + (v20 + v30);
        a1 += (v01 + v11) + (v21 + v31);
        a2 += (v02 + v12) + (v22 + v32);
    }
    for (; e < end; e++) {
        const float* r = g_h + (size_t)g_esrc[e] * 96;
        a0 += r[lane]; a1 += r[lane + 32]; a2 += r[lane + 64];
    }
    float dw = g_dis[w];
    float* o = g_agg + (size_t)w * 96;
    if (!FINAL) {
        o[lane]      += a0 * dw;
        o[lane + 32] += a1 * dw;
        o[lane + 64] += a2 * dw;
    } else {
        float p0 = fmaxf(o[lane]      + a0 * dw + b2[lane],      0.0f);
        float p1 = fmaxf(o[lane + 32] + a1 * dw + b2[lane + 32], 0.0f);
        float p2 = fmaxf(o[lane + 64] + a2 * dw + b2[lane + 64], 0.0f);
        float* pl = g_pool + batch[w] * DH;
        atomicAdd(pl + lane,      p0);
        atomicAdd(pl + lane + 32, p1);
        atomicAdd(pl + lane + 64, p2);
    }
}

// ---------------- head: counts via binary search on sorted batch -------------
__global__ void k_fc(const float* __restrict__ Wfc, const float* __restrict__ bfc,
                     const int* __restrict__ batch, float* __restrict__ out)
{
    int t = threadIdx.x;
    if (t >= GG * DOUT) return;
    int g = t >> 1, o = t & 1;
    // count of nodes with batch[i] == g (batch sorted ascending)
    int lo = 0, hi = NN;
    while (lo < hi) { int m = (lo + hi) >> 1; if (batch[m] < g) lo = m + 1; else hi = m; }
    int lb = lo;
    lo = 0; hi = NN;
    while (lo < hi) { int m = (lo + hi) >> 1; if (batch[m] <= g) lo = m + 1; else hi = m; }
    float cn = fmaxf((float)(lo - lb), 1.0f);
    float s = bfc[o];
    for (int c = 0; c < DH; c++)
        s += (g_pool[g * DH + c] / cn) * Wfc[c * DOUT + o];
    out[g * DOUT + o] = s;
}

// ---------------- launch ------------------------------------------------------
extern "C" void kernel_launch(void* const* d_in, const int* in_sizes, int n_in,
                              void* d_out, int out_size)
{
    const float* x    = (const float*)d_in[0];
    const float* W1   = (const float*)d_in[1];
    const float* b1   = (const float*)d_in[2];
    const float* W2   = (const float*)d_in[3];
    const float* b2   = (const float*)d_in[4];
    const float* Wfc  = (const float*)d_in[5];
    const float* bfc  = (const float*)d_in[6];
    const int*   src  = (const int*)d_in[7];
    const int*   dst  = (const int*)d_in[8];
    const int*   batch= (const int*)d_in[9];
    float* out = (float*)d_out;

    const int nb_n = (NN + 255) / 256;
    const int nb_e = (EE + 255) / 256;
    const int nb_g = (NN + 127) / 128;
    const int nb_s = (NN * 32 + 255) / 256;   // one warp per node

    k_wsplit   <<<nb_n, 256>>>(W1, W2);       // + ncnt/pool init
    k_deg_count<<<nb_e, 256>>>(dst);
    k_scanA    <<<SCB, 256>>>();
    k_scanC    <<<SCB, 256>>>();              // + dis = rsqrt(1+cnt)
    k_reorder  <<<nb_e, 256>>>(src, dst);

    // layer 1
    k_gemm<DIN, false, false, 1><<<nb_g, 256>>>(x, b1);
    k_scatter_csr<false><<<nb_s, 256>>>(b2, batch);

    // layer 2 (scatter fused with relu+bias+pool)
    k_gemm<DH, true, true, 2><<<nb_g, 256>>>(nullptr, b1);
    k_scatter_csr<true><<<nb_s, 256>>>(b2, batch);

    k_fc<<<1, 128>>>(Wfc, bfc, batch, out);
}

// round 12
// speedup vs baseline: 1.3532x; 1.1247x over previous
#include <cuda_runtime.h>
#include <cuda_bf16.h>
#include <math.h>

#define NN    50000
#define EE    800000
#define DIN   300
#define DH    96
#define DOUT  2
#define GG    64
#define SCB   196                    // scan blocks: ceil(50000/256)

// ---------------- scratch (device globals; no allocation allowed) -----------
__device__ float g_dis[NN];
__device__ float g_h  [(size_t)NN * DH];    // h * dis (pre-scaled!)
__device__ float g_agg[(size_t)NN * DH];
__device__ float g_pool[GG * DH];
__device__ __nv_bfloat16 g_W1h[DIN * DH], g_W1l[DIN * DH];
__device__ __nv_bfloat16 g_W2h[DH * DH],  g_W2l[DH * DH];
// CSR scratch
__device__ int      g_ncnt[NN];
__device__ int      g_tmp [NN];
__device__ int      g_bsum[256];
__device__ int      g_noff[NN + 1];
__device__ int      g_ncur[NN];
__device__ unsigned g_esrc[EE];      // src ids sorted by dst

// ---------------- weight split + init ---------------------------------------
__global__ void k_wsplit(const float* __restrict__ W1, const float* __restrict__ W2) {
    int i = blockIdx.x * blockDim.x + threadIdx.x;
    if (i < DIN * DH) {
        float f = W1[i];
        __nv_bfloat16 hi = __float2bfloat16(f);
        g_W1h[i] = hi;
        g_W1l[i] = __float2bfloat16(f - __bfloat162float(hi));
    }
    if (i < DH * DH) {
        float f = W2[i];
        __nv_bfloat16 hi = __float2bfloat16(f);
        g_W2h[i] = hi;
        g_W2l[i] = __float2bfloat16(f - __bfloat162float(hi));
    }
    if (i < NN) g_ncnt[i] = 0;
    if (i < GG * DH) g_pool[i] = 0.0f;
}
__global__ void k_deg_count(const int* __restrict__ dst) {
    int e = blockIdx.x * blockDim.x + threadIdx.x;
    if (e < EE) atomicAdd(&g_ncnt[dst[e]], 1);
}

// ---------------- scan (dis fused into C) ------------------------------------
__global__ void __launch_bounds__(256) k_scanA() {
    __shared__ int sh[256];
    int t  = threadIdx.x;
    int gi = blockIdx.x * 256 + t;
    int v  = (gi < NN) ? g_ncnt[gi] : 0;
    sh[t] = v; __syncthreads();
#pragma unroll
    for (int off = 1; off < 256; off <<= 1) {
        int u = (t >= off) ? sh[t - off] : 0;
        __syncthreads();
        sh[t] += u;
        __syncthreads();
    }
    if (gi < NN) g_tmp[gi] = sh[t];                   // inclusive within block
    if (t == 255) g_bsum[blockIdx.x] = sh[255];
}
__global__ void __launch_bounds__(256) k_scanC() {
    __shared__ int sb[256];
    int t = threadIdx.x;
    sb[t] = (t < SCB) ? g_bsum[t] : 0;
    __syncthreads();
#pragma unroll
    for (int off = 1; off < 256; off <<= 1) {
        int u = (t >= off) ? sb[t - off] : 0;
        __syncthreads();
        sb[t] += u;
        __syncthreads();
    }
    int gi = blockIdx.x * 256 + t;
    if (gi >= NN) return;
    int base = (blockIdx.x > 0) ? sb[blockIdx.x - 1] : 0;
    int cnt  = g_ncnt[gi];
    int inc  = g_tmp[gi] + base;
    g_noff[gi + 1] = inc;
    g_ncur[gi]     = inc - cnt;
    g_dis[gi]      = rsqrtf(1.0f + (float)cnt);       // fused deg_finish
    if (gi == 0) g_noff[0] = 0;
}
__global__ void __launch_bounds__(256)
k_reorder(const int* __restrict__ src, const int* __restrict__ dst) {
    int e = blockIdx.x * blockDim.x + threadIdx.x;
    if (e >= EE) return;
    int pos = atomicAdd(&g_ncur[dst[e]], 1);
    g_esrc[pos] = (unsigned)src[e];
}

// ---------------- mma helpers ------------------------------------------------
__device__ __forceinline__ unsigned smem_u32(const void* p) {
    return (unsigned)__cvta_generic_to_shared(p);
}
#define LDSM_X4(r, addr) \
    asm volatile("ldmatrix.sync.aligned.m8n8.x4.shared.b16 {%0,%1,%2,%3},[%4];" \
                 : "=r"((r)[0]), "=r"((r)[1]), "=r"((r)[2]), "=r"((r)[3]) : "r"(addr))
#define LDSM_X2_T(r, addr) \
    asm volatile("ldmatrix.sync.aligned.m8n8.x2.trans.shared.b16 {%0,%1},[%2];" \
                 : "=r"((r)[0]), "=r"((r)[1]) : "r"(addr))
#define MMA_BF16(d, a, b) \
    asm volatile("mma.sync.aligned.m16n8k16.row.col.f32.bf16.bf16.f32 " \
                 "{%0,%1,%2,%3},{%4,%5,%6,%7},{%8,%9},{%0,%1,%2,%3};" \
                 : "+f"((d)[0]), "+f"((d)[1]), "+f"((d)[2]), "+f"((d)[3]) \
                 : "r"((a)[0]), "r"((a)[1]), "r"((a)[2]), "r"((a)[3]), \
                   "r"((b)[0]), "r"((b)[1]))

// ---------------- pipelined bf16-split tensor GEMM: out = in @ W ------------
// (R8-proven form.) Epilogue: g_h = acc*dis; g_agg = acc*dis^2.
template <int K, bool RELU_BIAS, bool IN_IS_AGG, int WSEL>
__global__ void __launch_bounds__(256, 2)
k_gemm(const float* __restrict__ in, const float* __restrict__ bias)
{
    __shared__ __nv_bfloat16 Ah[2][128 * 24], Al[2][128 * 24];
    __shared__ __nv_bfloat16 Bh[2][16 * 104], Bl[2][16 * 104];
    __shared__ float bs[DH];

    const int tid  = threadIdx.x;
    const int lane = tid & 31;
    const int wid  = tid >> 5;
    const int wm   = wid & 3;
    const int wn   = wid >> 2;
    const int r0   = blockIdx.x * 128;
    const int gidx = lane >> 2;
    const int tidx = lane & 3;

    const float* __restrict__ src_in = IN_IS_AGG ? (const float*)g_agg : in;
    const uint4* __restrict__ Wh4 =
        (const uint4*)(WSEL == 1 ? (const void*)g_W1h : (const void*)g_W2h);
    const uint4* __restrict__ Wl4 =
        (const uint4*)(WSEL == 1 ? (const void*)g_W1l : (const void*)g_W2l);

    if (RELU_BIAS) { if (tid < DH) bs[tid] = bias[tid]; }

    float acc[2][6][4];
#pragma unroll
    for (int mt = 0; mt < 2; mt++)
#pragma unroll
        for (int nt = 0; nt < 6; nt++)
#pragma unroll
            for (int q = 0; q < 4; q++) acc[mt][nt][q] = 0.0f;

    unsigned a_h0[2], a_l0[2];
#pragma unroll
    for (int mt = 0; mt < 2; mt++) {
        int row = wm * 32 + mt * 16 + (lane & 15);
        int col = (lane >> 4) * 8;
        a_h0[mt] = smem_u32(&Ah[0][row * 24 + col]);
        a_l0[mt] = smem_u32(&Al[0][row * 24 + col]);
    }
    unsigned b_h0[6], b_l0[6];
#pragma unroll
    for (int nt = 0; nt < 6; nt++) {
        int krow  = lane & 15;
        int cbase = wn * 48 + nt * 8;
        b_h0[nt] = smem_u32(&Bh[0][krow * 104 + cbase]);
        b_l0[nt] = smem_u32(&Bl[0][krow * 104 + cbase]);
    }
    const unsigned A_STRIDE = 128 * 24 * 2;
    const unsigned B_STRIDE = 16 * 104 * 2;

    float4 pa[2];
    uint4  pb[2];

    auto load_stage = [&](int k0) {
#pragma unroll
        for (int t = 0; t < 2; t++) {
            int idx = tid + t * 256;
            int row = idx >> 2, q = idx & 3;
            int gr = r0 + row, gk = k0 + q * 4;
            pa[t] = make_float4(0.f, 0.f, 0.f, 0.f);
            if (gr < NN && gk + 4 <= K)
                pa[t] = *reinterpret_cast<const float4*>(src_in + (size_t)gr * K + gk);
        }
#pragma unroll
        for (int t = 0; t < 2; t++) {
            int idx = tid + t * 256;
            if (idx < 384) {
                int half = (idx >= 192);
                int j  = idx - half * 192;
                int kk = j / 12, c = j % 12;
                int gk = k0 + kk;
                pb[t] = make_uint4(0u, 0u, 0u, 0u);
                if (gk < K)
                    pb[t] = (half ? Wl4 : Wh4)[gk * 12 + c];
            }
        }
    };

    auto store_stage = [&](int buf, int k0) {
#pragma unroll
        for (int t = 0; t < 2; t++) {
            int idx = tid + t * 256;
            int row = idx >> 2, q = idx & 3;
            float e[4] = {pa[t].x, pa[t].y, pa[t].z, pa[t].w};
            unsigned hp[2], lp[2];
#pragma unroll
            for (int p = 0; p < 2; p++) {
                float f0 = e[p * 2], f1 = e[p * 2 + 1];
                if (RELU_BIAS) {
                    int gk = k0 + q * 4 + p * 2;
                    f0 = fmaxf(f0 + bs[gk], 0.0f);
                    f1 = fmaxf(f1 + bs[gk + 1], 0.0f);
                }
                __nv_bfloat162 h2 = make_bfloat162(__float2bfloat16(f0),
                                                   __float2bfloat16(f1));
                __nv_bfloat162 l2 = make_bfloat162(
                    __float2bfloat16(f0 - __bfloat162float(h2.x)),
                    __float2bfloat16(f1 - __bfloat162float(h2.y)));
                hp[p] = *reinterpret_cast<unsigned*>(&h2);
                lp[p] = *reinterpret_cast<unsigned*>(&l2);
            }
            *reinterpret_cast<uint2*>(&Ah[buf][row * 24 + q * 4]) = make_uint2(hp[0], hp[1]);
            *reinterpret_cast<uint2*>(&Al[buf][row * 24 + q * 4]) = make_uint2(lp[0], lp[1]);
        }
#pragma unroll
        for (int t = 0; t < 2; t++) {
            int idx = tid + t * 256;
            if (idx < 384) {
                int half = (idx >= 192);
                int j  = idx - half * 192;
                int kk = j / 12, c = j % 12;
                __nv_bfloat16* dstp = half ? Bl[buf] : Bh[buf];
                *reinterpret_cast<uint4*>(&dstp[kk * 104 + c * 8]) = pb[t];
            }
        }
    };

    const int nstage = (K + 15) / 16;
    load_stage(0);
    __syncthreads();

    for (int s = 0; s < nstage; s++) {
        const int buf = s & 1;
        store_stage(buf, s * 16);
        __syncthreads();
        if (s + 1 < nstage) load_stage((s + 1) * 16);

        const unsigned ao = buf * A_STRIDE, bo = buf * B_STRIDE;
        unsigned ah[2][4], al[2][4], bh[6][2], bl[6][2];
#pragma unroll
        for (int mt = 0; mt < 2; mt++) {
            LDSM_X4(ah[mt], a_h0[mt] + ao);
            LDSM_X4(al[mt], a_l0[mt] + ao);
        }
#pragma unroll
        for (int nt = 0; nt < 6; nt++) {
            LDSM_X2_T(bh[nt], b_h0[nt] + bo);
            LDSM_X2_T(bl[nt], b_l0[nt] + bo);
        }
#pragma unroll
        for (int mt = 0; mt < 2; mt++)
#pragma unroll
            for (int nt = 0; nt < 6; nt++) {
                MMA_BF16(acc[mt][nt], ah[mt], bh[nt]);
                MMA_BF16(acc[mt][nt], ah[mt], bl[nt]);
                MMA_BF16(acc[mt][nt], al[mt], bh[nt]);
            }
    }

#pragma unroll
    for (int mt = 0; mt < 2; mt++) {
        int rbase = r0 + wm * 32 + mt * 16 + gidx;
#pragma unroll
        for (int half = 0; half < 2; half++) {
            int r = rbase + half * 8;
            if (r >= NN) continue;
            float ds = g_dis[r];
            float d2 = ds * ds;
#pragma unroll
            for (int nt = 0; nt < 6; nt++) {
                int c = wn * 48 + nt * 8 + tidx * 2;
                float v0 = acc[mt][nt][half * 2 + 0];
                float v1 = acc[mt][nt][half * 2 + 1];
                size_t o = (size_t)r * 96 + c;
                *reinterpret_cast<float2*>(g_h + o)   = make_float2(v0 * ds, v1 * ds);
                *reinterpret_cast<float2*>(g_agg + o) = make_float2(v0 * d2, v1 * d2);
            }
        }
    }
}

// ---------------- CSR scatter: one warp per dst node -------------------------
// FINAL=false: g_agg[w] += sum * dis[w]  (layer 1)
// FINAL=true : pooling fused: block aggregates its 8 consecutive nodes' rows
//              in smem (batch sorted -> 1-2 distinct graphs/block), then emits
//              run-length-compressed atomics to g_pool.
// NOTE: NN = 50000 = 6250 blocks * 8 warps exactly -> no partial blocks.
template <bool FINAL>
__global__ void __launch_bounds__(256)
k_scatter_csr(const float* __restrict__ b2, const int* __restrict__ batch)
{
    int w    = (blockIdx.x * 256 + threadIdx.x) >> 5;   // node id
    int lane = threadIdx.x & 31;
    int wb   = (threadIdx.x >> 5);                      // warp within block
    if (!FINAL && w >= NN) return;

    const int beg = g_noff[w], end = g_noff[w + 1];

    float a0 = 0.f, a1 = 0.f, a2 = 0.f;
    int e = beg;
    for (; e + 4 <= end; e += 4) {
        unsigned s0 = g_esrc[e],     s1 = g_esrc[e + 1];
        unsigned s2 = g_esrc[e + 2], s3 = g_esrc[e + 3];
        const float* r0 = g_h + (size_t)s0 * 96;
        const float* r1 = g_h + (size_t)s1 * 96;
        const float* r2 = g_h + (size_t)s2 * 96;
        const float* r3 = g_h + (size_t)s3 * 96;
        float v00 = r0[lane], v01 = r0[lane + 32], v02 = r0[lane + 64];
        float v10 = r1[lane], v11 = r1[lane + 32], v12 = r1[lane + 64];
        float v20 = r2[lane], v21 = r2[lane + 32], v22 = r2[lane + 64];
        float v30 = r3[lane], v31 = r3[lane + 32], v32 = r3[lane + 64];
        a0 += (v00 + v10) + (v20 + v30);
        a1 += (v01 + v11) + (v21 + v31);
        a2 += (v02 + v12) + (v22 + v32);
    }
    for (; e < end; e++) {
        const float* r = g_h + (size_t)g_esrc[e] * 96;
        a0 += r[lane]; a1 += r[lane + 32]; a2 += r[lane + 64];
    }
    float dw = g_dis[w];
    if (!FINAL) {
        float* o = g_agg + (size_t)w * 96;
        o[lane]      += a0 * dw;
        o[lane + 32] += a1 * dw;
        o[lane + 64] += a2 * dw;
    } else {
        __shared__ float sp[8][96];
        __shared__ int   sg[8];
        const float* o = g_agg + (size_t)w * 96;
        sp[wb][lane]      = fmaxf(o[lane]      + a0 * dw + b2[lane],      0.0f);
        sp[wb][lane + 32] = fmaxf(o[lane + 32] + a1 * dw + b2[lane + 32], 0.0f);
        sp[wb][lane + 64] = fmaxf(o[lane + 64] + a2 * dw + b2[lane + 64], 0.0f);
        if (lane == 0) sg[wb] = batch[w];
        __syncthreads();
        // run-length compressed pool atomics (batch sorted)
        int c = threadIdx.x;
        if (c < 96) {
            float acc = sp[0][c];
            int   cur = sg[0];
#pragma unroll
            for (int j = 1; j < 8; j++) {
                int gj = sg[j];
                if (gj != cur) {
                    atomicAdd(&g_pool[cur * DH + c], acc);
                    acc = 0.0f; cur = gj;
                }
                acc += sp[j][c];
            }
            atomicAdd(&g_pool[cur * DH + c], acc);
        }
    }
}

// ---------------- head: counts via binary search on sorted batch -------------
__global__ void k_fc(const float* __restrict__ Wfc, const float* __restrict__ bfc,
                     const int* __restrict__ batch, float* __restrict__ out)
{
    int t = threadIdx.x;
    if (t >= GG * DOUT) return;
    int g = t >> 1, o = t & 1;
    int lo = 0, hi = NN;
    while (lo < hi) { int m = (lo + hi) >> 1; if (batch[m] < g) lo = m + 1; else hi = m; }
    int lb = lo;
    lo = 0; hi = NN;
    while (lo < hi) { int m = (lo + hi) >> 1; if (batch[m] <= g) lo = m + 1; else hi = m; }
    float cn = fmaxf((float)(lo - lb), 1.0f);
    float s = bfc[o];
    for (int c = 0; c < DH; c++)
        s += (g_pool[g * DH + c] / cn) * Wfc[c * DOUT + o];
    out[g * DOUT + o] = s;
}

// ---------------- launch ------------------------------------------------------
extern "C" void kernel_launch(void* const* d_in, const int* in_sizes, int n_in,
                              void* d_out, int out_size)
{
    const float* x    = (const float*)d_in[0];
    const float* W1   = (const float*)d_in[1];
    const float* b1   = (const float*)d_in[2];
    const float* W2   = (const float*)d_in[3];
    const float* b2   = (const float*)d_in[4];
    const float* Wfc  = (const float*)d_in[5];
    const float* bfc  = (const float*)d_in[6];
    const int*   src  = (const int*)d_in[7];
    const int*   dst  = (const int*)d_in[8];
    const int*   batch= (const int*)d_in[9];
    float* out = (float*)d_out;

    const int nb_n = (NN + 255) / 256;
    const int nb_e = (EE + 255) / 256;
    const int nb_g = (NN + 127) / 128;
    const int nb_s = (NN * 32 + 255) / 256;   // one warp per node (6250, exact)

    k_wsplit   <<<nb_n, 256>>>(W1, W2);       // + ncnt/pool init
    k_deg_count<<<nb_e, 256>>>(dst);
    k_scanA    <<<SCB, 256>>>();
    k_scanC    <<<SCB, 256>>>();              // + dis = rsqrt(1+cnt)
    k_reorder  <<<nb_e, 256>>>(src, dst);

    // layer 1
    k_gemm<DIN, false, false, 1><<<nb_g, 256>>>(x, b1);
    k_scatter_csr<false><<<nb_s, 256>>>(b2, batch);

    // layer 2 (scatter fused with relu+bias+pool, block-aggregated atomics)
    k_gemm<DH, true, true, 2><<<nb_g, 256>>>(nullptr, b1);
    k_scatter_csr<true><<<nb_s, 256>>>(b2, batch);

    k_fc<<<1, 128>>>(Wfc, bfc, batch, out);
}

// round 14
// speedup vs baseline: 1.4028x; 1.0366x over previous
#include <cuda_runtime.h>
#include <cuda_bf16.h>
#include <math.h>

#define NN    50000
#define EE    800000
#define DIN   300
#define DH    96
#define DOUT  2
#define GG    64
#define SCB   196                    // scan blocks: ceil(50000/256)

// ---------------- scratch (device globals; zero-initialized at load) --------
// INVARIANT: g_ncnt is ZERO on entry to every kernel_launch call: statically
// zero-initialized for the first call, re-zeroed at the END of each call by
// k_fc_fin blocks 1.. (g_ncnt is NOT read by the fc block -> no race).
// g_pool is zeroed at the START of each call by k_prep (written only later).
__device__ float g_dis[NN];
__device__ float g_h  [(size_t)NN * DH];    // h * dis (pre-scaled!)
__device__ float g_agg[(size_t)NN * DH];
__device__ float g_pool[GG * DH];
__device__ __nv_bfloat16 g_W1h[DIN * DH], g_W1l[DIN * DH];
__device__ __nv_bfloat16 g_W2h[DH * DH],  g_W2l[DH * DH];
// CSR scratch
__device__ int      g_ncnt[NN];
__device__ int      g_tmp [NN];
__device__ int      g_bsum[256];
__device__ int      g_noff[NN + 1];
__device__ int      g_ncur[NN];
__device__ unsigned g_esrc[EE];      // src ids sorted by dst

// ---------------- prep: weight split + degree count + pool zero -------------
__global__ void __launch_bounds__(256)
k_prep(const float* __restrict__ W1, const float* __restrict__ W2,
       const int* __restrict__ dst)
{
    int i = blockIdx.x * blockDim.x + threadIdx.x;
    if (i < DIN * DH) {
        float f = W1[i];
        __nv_bfloat16 hi = __float2bfloat16(f);
        g_W1h[i] = hi;
        g_W1l[i] = __float2bfloat16(f - __bfloat162float(hi));
    }
    if (i < DH * DH) {
        float f = W2[i];
        __nv_bfloat16 hi = __float2bfloat16(f);
        g_W2h[i] = hi;
        g_W2l[i] = __float2bfloat16(f - __bfloat162float(hi));
    }
    if (i < GG * DH) g_pool[i] = 0.0f;           // pool written only later
    if (i < EE) atomicAdd(&g_ncnt[dst[i]], 1);   // g_ncnt zero on entry
}

// ---------------- scan (dis fused into C) ------------------------------------
__global__ void __launch_bounds__(256) k_scanA() {
    __shared__ int sh[256];
    int t  = threadIdx.x;
    int gi = blockIdx.x * 256 + t;
    int v  = (gi < NN) ? g_ncnt[gi] : 0;
    sh[t] = v; __syncthreads();
#pragma unroll
    for (int off = 1; off < 256; off <<= 1) {
        int u = (t >= off) ? sh[t - off] : 0;
        __syncthreads();
        sh[t] += u;
        __syncthreads();
    }
    if (gi < NN) g_tmp[gi] = sh[t];                   // inclusive within block
    if (t == 255) g_bsum[blockIdx.x] = sh[255];
}
__global__ void __launch_bounds__(256) k_scanC() {
    __shared__ int sb[256];
    int t = threadIdx.x;
    sb[t] = (t < SCB) ? g_bsum[t] : 0;
    __syncthreads();
#pragma unroll
    for (int off = 1; off < 256; off <<= 1) {
        int u = (t >= off) ? sb[t - off] : 0;
        __syncthreads();
        sb[t] += u;
        __syncthreads();
    }
    int gi = blockIdx.x * 256 + t;
    if (gi >= NN) return;
    int base = (blockIdx.x > 0) ? sb[blockIdx.x - 1] : 0;
    int cnt  = g_ncnt[gi];
    int inc  = g_tmp[gi] + base;
    g_noff[gi + 1] = inc;
    g_ncur[gi]     = inc - cnt;
    g_dis[gi]      = rsqrtf(1.0f + (float)cnt);       // fused deg_finish
    if (gi == 0) g_noff[0] = 0;
}
__global__ void __launch_bounds__(256)
k_reorder(const int* __restrict__ src, const int* __restrict__ dst) {
    int e = blockIdx.x * blockDim.x + threadIdx.x;
    if (e >= EE) return;
    int pos = atomicAdd(&g_ncur[dst[e]], 1);
    g_esrc[pos] = (unsigned)src[e];
}

// ---------------- mma / cp.async helpers --------------------------------------
__device__ __forceinline__ unsigned smem_u32(const void* p) {
    return (unsigned)__cvta_generic_to_shared(p);
}
#define LDSM_X4(r, addr) \
    asm volatile("ldmatrix.sync.aligned.m8n8.x4.shared.b16 {%0,%1,%2,%3},[%4];" \
                 : "=r"((r)[0]), "=r"((r)[1]), "=r"((r)[2]), "=r"((r)[3]) : "r"(addr))
#define LDSM_X2_T(r, addr) \
    asm volatile("ldmatrix.sync.aligned.m8n8.x2.trans.shared.b16 {%0,%1},[%2];" \
                 : "=r"((r)[0]), "=r"((r)[1]) : "r"(addr))
#define MMA_BF16(d, a, b) \
    asm volatile("mma.sync.aligned.m16n8k16.row.col.f32.bf16.bf16.f32 " \
                 "{%0,%1,%2,%3},{%4,%5,%6,%7},{%8,%9},{%0,%1,%2,%3};" \
                 : "+f"((d)[0]), "+f"((d)[1]), "+f"((d)[2]), "+f"((d)[3]) \
                 : "r"((a)[0]), "r"((a)[1]), "r"((a)[2]), "r"((a)[3]), \
                   "r"((b)[0]), "r"((b)[1]))
#define CP_ASYNC16(dst, src, sz) \
    asm volatile("cp.async.cg.shared.global [%0], [%1], 16, %2;" \
                 :: "r"(dst), "l"(src), "r"(sz) : "memory")
#define CP_COMMIT() asm volatile("cp.async.commit_group;" ::: "memory")
#define CP_WAIT2()  asm volatile("cp.async.wait_group 2;" ::: "memory")

// dynamic smem layout (bytes)
#define XS_OFF   0                       // float Xs[3][128*16]   = 24576
#define AH_OFF   24576                   // bf16  Ah[2][128*24]   = 12288
#define AL_OFF   36864                   // bf16  Al[2][128*24]   = 12288
#define BH_OFF   49152                   // bf16  Bh[2][16*104]   =  6656
#define BL_OFF   55808                   // bf16  Bl[2][16*104]   =  6656
#define BS_OFF   62464                   // float bs[96]          =   384
#define SMEM_TOT 62848

// ---------------- cp.async-pipelined bf16-split tensor GEMM -----------------
// BM=128 BN=96 BK=16, 8 warps (4Mx2N). A tile: 3-deep cp.async fp32 staging,
// converted to bf16 hi/lo per stage (each thread converts only its OWN copied
// chunks -> no barrier between wait and convert). B: register prefetch of
// pre-split bf16 weights (L2-hot). One __syncthreads per stage.
// Epilogue: g_h = acc*dis; g_agg = acc*dis^2.
template <int K, bool RELU_BIAS, bool IN_IS_AGG, int WSEL>
__global__ void __launch_bounds__(256, 2)
k_gemm(const float* __restrict__ in, const float* __restrict__ bias)
{
    extern __shared__ char smem_raw[];
    float*         Xs = (float*)(smem_raw + XS_OFF);          // [3][2048]
    __nv_bfloat16* Ah = (__nv_bfloat16*)(smem_raw + AH_OFF);  // [2][3072]
    __nv_bfloat16* Al = (__nv_bfloat16*)(smem_raw + AL_OFF);
    __nv_bfloat16* Bh = (__nv_bfloat16*)(smem_raw + BH_OFF);  // [2][1664]
    __nv_bfloat16* Bl = (__nv_bfloat16*)(smem_raw + BL_OFF);
    float*         bs = (float*)(smem_raw + BS_OFF);

    const int tid  = threadIdx.x;
    const int lane = tid & 31;
    const int wid  = tid >> 5;
    const int wm   = wid & 3;
    const int wn   = wid >> 2;
    const int r0   = blockIdx.x * 128;
    const int gidx = lane >> 2;
    const int tidx = lane & 3;

    const float* __restrict__ src_in = IN_IS_AGG ? (const float*)g_agg : in;
    const uint4* __restrict__ Wh4 =
        (const uint4*)(WSEL == 1 ? (const void*)g_W1h : (const void*)g_W2h);
    const uint4* __restrict__ Wl4 =
        (const uint4*)(WSEL == 1 ? (const void*)g_W1l : (const void*)g_W2l);

    if (RELU_BIAS) { if (tid < DH) bs[tid] = bias[tid]; }

    float acc[2][6][4];
#pragma unroll
    for (int mt = 0; mt < 2; mt++)
#pragma unroll
        for (int nt = 0; nt < 6; nt++)
#pragma unroll
            for (int q = 0; q < 4; q++) acc[mt][nt][q] = 0.0f;

    unsigned a_h0[2], a_l0[2];
#pragma unroll
    for (int mt = 0; mt < 2; mt++) {
        int row = wm * 32 + mt * 16 + (lane & 15);
        int col = (lane >> 4) * 8;
        a_h0[mt] = smem_u32(&Ah[row * 24 + col]);
        a_l0[mt] = smem_u32(&Al[row * 24 + col]);
    }
    unsigned b_h0[6], b_l0[6];
#pragma unroll
    for (int nt = 0; nt < 6; nt++) {
        int krow  = lane & 15;
        int cbase = wn * 48 + nt * 8;
        b_h0[nt] = smem_u32(&Bh[krow * 104 + cbase]);
        b_l0[nt] = smem_u32(&Bl[krow * 104 + cbase]);
    }
    const unsigned A_STRIDE = 128 * 24 * 2;   // bytes per Ah/Al buffer
    const unsigned B_STRIDE = 16 * 104 * 2;   // bytes per Bh/Bl buffer
    const unsigned xs_u32   = smem_u32(Xs);

    auto issue_x = [&](int stage) {
        const int k0 = stage * 16;
        const unsigned xb = (unsigned)(stage % 3);
#pragma unroll
        for (int t = 0; t < 2; t++) {
            int idx = tid + t * 256;
            int row = idx >> 2, q = idx & 3;
            int gr = r0 + row, gk = k0 + q * 4;
            const float* src = src_in + (size_t)gr * K + gk;
            int sz = (gr < NN && gk + 4 <= K) ? 16 : 0;
            if (sz == 0) src = src_in;                 // keep address valid
            CP_ASYNC16(xs_u32 + xb * 8192u + (unsigned)idx * 16u, src, sz);
        }
    };

    uint4 pb[2];
    auto load_pb = [&](int stage) {
        const int k0 = stage * 16;
#pragma unroll
        for (int t = 0; t < 2; t++) {
            int idx = tid + t * 256;
            if (idx < 384) {
                int half = (idx >= 192);
                int j  = idx - half * 192;
                int kk = j / 12, c = j % 12;
                int gk = k0 + kk;
                pb[t] = make_uint4(0u, 0u, 0u, 0u);
                if (gk < K)
                    pb[t] = (half ? Wl4 : Wh4)[gk * 12 + c];
            }
        }
    };

    const int nstage = (K + 15) / 16;    // 19 or 6; always >= 4
    issue_x(0); CP_COMMIT();
    issue_x(1); CP_COMMIT();
    issue_x(2); CP_COMMIT();
    load_pb(0);
    __syncthreads();                     // bs visible before first convert

    for (int s = 0; s < nstage; s++) {
        const int buf = s & 1;
        const int xb  = s % 3;
        CP_WAIT2();                      // my stage-s Xs chunks arrived
        // convert MY chunks fp32 -> bf16 hi/lo (own data: no barrier needed)
        {
            const float* xsrc = Xs + xb * 2048;
#pragma unroll
            for (int t = 0; t < 2; t++) {
                int idx = tid + t * 256;
                int row = idx >> 2, q = idx & 3;
                float4 v = *reinterpret_cast<const float4*>(xsrc + idx * 4);
                float e[4] = {v.x, v.y, v.z, v.w};
                unsigned hp[2], lp[2];
#pragma unroll
                for (int p = 0; p < 2; p++) {
                    float f0 = e[p * 2], f1 = e[p * 2 + 1];
                    if (RELU_BIAS) {
                        int gk = s * 16 + q * 4 + p * 2;
                        f0 = fmaxf(f0 + bs[gk], 0.0f);
                        f1 = fmaxf(f1 + bs[gk + 1], 0.0f);
                    }
                    __nv_bfloat162 h2 = make_bfloat162(__float2bfloat16(f0),
                                                       __float2bfloat16(f1));
                    __nv_bfloat162 l2 = make_bfloat162(
                        __float2bfloat16(f0 - __bfloat162float(h2.x)),
                        __float2bfloat16(f1 - __bfloat162float(h2.y)));
                    hp[p] = *reinterpret_cast<unsigned*>(&h2);
                    lp[p] = *reinterpret_cast<unsigned*>(&l2);
                }
                *reinterpret_cast<uint2*>(&Ah[buf * 3072 + row * 24 + q * 4]) =
                    make_uint2(hp[0], hp[1]);
                *reinterpret_cast<uint2*>(&Al[buf * 3072 + row * 24 + q * 4]) =
                    make_uint2(lp[0], lp[1]);
            }
        }
        if (s + 3 < nstage) issue_x(s + 3);   // reuse Xs[xb] (my chunks consumed)
        CP_COMMIT();                          // exactly one group per iteration
        // stage B regs -> smem
#pragma unroll
        for (int t = 0; t < 2; t++) {
            int idx = tid + t * 256;
            if (idx < 384) {
                int half = (idx >= 192);
                int j  = idx - half * 192;
                int kk = j / 12, c = j % 12;
                __nv_bfloat16* dstp = (half ? Bl : Bh) + buf * 1664;
                *reinterpret_cast<uint4*>(&dstp[kk * 104 + c * 8]) = pb[t];
            }
        }
        __syncthreads();
        if (s + 1 < nstage) load_pb(s + 1);

        const unsigned ao = buf * A_STRIDE, bo = buf * B_STRIDE;
        unsigned ah[2][4], al[2][4], bh[6][2], bl[6][2];
#pragma unroll
        for (int mt = 0; mt < 2; mt++) {
            LDSM_X4(ah[mt], a_h0[mt] + ao);
            LDSM_X4(al[mt], a_l0[mt] + ao);
        }
#pragma unroll
        for (int nt = 0; nt < 6; nt++) {
            LDSM_X2_T(bh[nt], b_h0[nt] + bo);
            LDSM_X2_T(bl[nt], b_l0[nt] + bo);
        }
#pragma unroll
        for (int mt = 0; mt < 2; mt++)
#pragma unroll
            for (int nt = 0; nt < 6; nt++) {
                MMA_BF16(acc[mt][nt], ah[mt], bh[nt]);
                MMA_BF16(acc[mt][nt], ah[mt], bl[nt]);
                MMA_BF16(acc[mt][nt], al[mt], bh[nt]);
            }
    }

#pragma unroll
    for (int mt = 0; mt < 2; mt++) {
        int rbase = r0 + wm * 32 + mt * 16 + gidx;
#pragma unroll
        for (int half = 0; half < 2; half++) {
            int r = rbase + half * 8;
            if (r >= NN) continue;
            float ds = g_dis[r];
            float d2 = ds * ds;
#pragma unroll
            for (int nt = 0; nt < 6; nt++) {
                int c = wn * 48 + nt * 8 + tidx * 2;
                float v0 = acc[mt][nt][half * 2 + 0];
                float v1 = acc[mt][nt][half * 2 + 1];
                size_t o = (size_t)r * 96 + c;
                *reinterpret_cast<float2*>(g_h + o)   = make_float2(v0 * ds, v1 * ds);
                *reinterpret_cast<float2*>(g_agg + o) = make_float2(v0 * d2, v1 * d2);
            }
        }
    }
}

// ---------------- CSR scatter: one warp per dst node -------------------------
// FINAL=false: g_agg[w] += sum * dis[w]  (layer 1)
// FINAL=true : pooling fused with block-level run-length aggregation.
// NOTE: NN = 50000 = 6250 blocks * 8 warps exactly -> no partial blocks.
template <bool FINAL>
__global__ void __launch_bounds__(256)
k_scatter_csr(const float* __restrict__ b2, const int* __restrict__ batch)
{
    int w    = (blockIdx.x * 256 + threadIdx.x) >> 5;   // node id
    int lane = threadIdx.x & 31;
    int wb   = (threadIdx.x >> 5);                      // warp within block
    if (!FINAL && w >= NN) return;

    const int beg = g_noff[w], end = g_noff[w + 1];

    float a0 = 0.f, a1 = 0.f, a2 = 0.f;
    int e = beg;
    for (; e + 4 <= end; e += 4) {
        unsigned s0 = g_esrc[e],     s1 = g_esrc[e + 1];
        unsigned s2 = g_esrc[e + 2], s3 = g_esrc[e + 3];
        const float* r0 = g_h + (size_t)s0 * 96;
        const float* r1 = g_h + (size_t)s1 * 96;
        const float* r2 = g_h + (size_t)s2 * 96;
        const float* r3 = g_h + (size_t)s3 * 96;
        float v00 = r0[lane], v01 = r0[lane + 32], v02 = r0[lane + 64];
        float v10 = r1[lane], v11 = r1[lane + 32], v12 = r1[lane + 64];
        float v20 = r2[lane], v21 = r2[lane + 32], v22 = r2[lane + 64];
        float v30 = r3[lane], v31 = r3[lane + 32], v32 = r3[lane + 64];
        a0 += (v00 + v10) + (v20 + v30);
        a1 += (v01 + v11) + (v21 + v31);
        a2 += (v02 + v12) + (v22 + v32);
    }
    for (; e < end; e++) {
        const float* r = g_h + (size_t)g_esrc[e] * 96;
        a0 += r[lane]; a1 += r[lane + 32]; a2 += r[lane + 64];
    }
    float dw = g_dis[w];
    if (!FINAL) {
        float* o = g_agg + (size_t)w * 96;
        o[lane]      += a0 * dw;
        o[lane + 32] += a1 * dw;
        o[lane + 64] += a2 * dw;
    } else {
        __shared__ float sp[8][96];
        __shared__ int   sg[8];
        const float* o = g_agg + (size_t)w * 96;
        sp[wb][lane]      = fmaxf(o[lane]      + a0 * dw + b2[lane],      0.0f);
        sp[wb][lane + 32] = fmaxf(o[lane + 32] + a1 * dw + b2[lane + 32], 0.0f);
        sp[wb][lane + 64] = fmaxf(o[lane + 64] + a2 * dw + b2[lane + 64], 0.0f);
        if (lane == 0) sg[wb] = batch[w];
        __syncthreads();
        int c = threadIdx.x;
        if (c < 96) {
            float acc = sp[0][c];
            int   cur = sg[0];
#pragma unroll
            for (int j = 1; j < 8; j++) {
                int gj = sg[j];
                if (gj != cur) {
                    atomicAdd(&g_pool[cur * DH + c], acc);
                    acc = 0.0f; cur = gj;
                }
                acc += sp[j][c];
            }
            atomicAdd(&g_pool[cur * DH + c], acc);
        }
    }
}

// ---------------- head + g_ncnt re-zeroing for next call ---------------------
// Block 0: fc (reads g_pool only). Blocks 1..196: zero g_ncnt ONLY (g_ncnt is
// not read by block 0 -> no race; g_pool is re-zeroed by k_prep next call).
__global__ void __launch_bounds__(256)
k_fc_fin(const float* __restrict__ Wfc, const float* __restrict__ bfc,
         const int* __restrict__ batch, float* __restrict__ out)
{
    if (blockIdx.x == 0) {
        int t = threadIdx.x;
        if (t >= GG * DOUT) return;
        int g = t >> 1, o = t & 1;
        int lo = 0, hi = NN;
        while (lo < hi) { int m = (lo + hi) >> 1; if (batch[m] < g) lo = m + 1; else hi = m; }
        int lb = lo;
        lo = 0; hi = NN;
        while (lo < hi) { int m = (lo + hi) >> 1; if (batch[m] <= g) lo = m + 1; else hi = m; }
        float cn = fmaxf((float)(lo - lb), 1.0f);
        float s = bfc[o];
        for (int c = 0; c < DH; c++)
            s += (g_pool[g * DH + c] / cn) * Wfc[c * DOUT + o];
        out[g * DOUT + o] = s;
    } else {
        int i = (blockIdx.x - 1) * 256 + threadIdx.x;
        if (i < NN) g_ncnt[i] = 0;
    }
}

// ---------------- launch ------------------------------------------------------
extern "C" void kernel_launch(void* const* d_in, const int* in_sizes, int n_in,
                              void* d_out, int out_size)
{
    const float* x    = (const float*)d_in[0];
    const float* W1   = (const float*)d_in[1];
    const float* b1   = (const float*)d_in[2];
    const float* W2   = (const float*)d_in[3];
    const float* b2   = (const float*)d_in[4];
    const float* Wfc  = (const float*)d_in[5];
    const float* bfc  = (const float*)d_in[6];
    const int*   src  = (const int*)d_in[7];
    const int*   dst  = (const int*)d_in[8];
    const int*   batch= (const int*)d_in[9];
    float* out = (float*)d_out;

    const int nb_e = (EE + 255) / 256;
    const int nb_g = (NN + 127) / 128;
    const int nb_s = (NN * 32 + 255) / 256;   // one warp per node (6250, exact)

    cudaFuncSetAttribute(k_gemm<DIN, false, false, 1>,
                         cudaFuncAttributeMaxDynamicSharedMemorySize, SMEM_TOT);
    cudaFuncSetAttribute(k_gemm<DH, true, true, 2>,
                         cudaFuncAttributeMaxDynamicSharedMemorySize, SMEM_TOT);

    k_prep   <<<nb_e, 256>>>(W1, W2, dst);    // wsplit + pool zero + deg count
    k_scanA  <<<SCB, 256>>>();
    k_scanC  <<<SCB, 256>>>();                // + dis = rsqrt(1+cnt)
    k_reorder<<<nb_e, 256>>>(src, dst);

    // layer 1
    k_gemm<DIN, false, false, 1><<<nb_g, 256, SMEM_TOT>>>(x, b1);
    k_scatter_csr<false><<<nb_s, 256>>>(b2, batch);

    // layer 2 (scatter fused with relu+bias+pool, block-aggregated atomics)
    k_gemm<DH, true, true, 2><<<nb_g, 256, SMEM_TOT>>>(nullptr, b1);
    k_scatter_csr<true><<<nb_s, 256>>>(b2, batch);

    k_fc_fin<<<SCB + 1, 256>>>(Wfc, bfc, batch, out);   // fc + re-zero g_ncnt
}

// round 15
// speedup vs baseline: 1.4378x; 1.0250x over previous
#include <cuda_runtime.h>
#include <cuda_bf16.h>
#include <math.h>

#define NN    50000
#define EE    800000
#define DIN   300
#define DH    96
#define DOUT  2
#define GG    64
#define SCB   196                    // scan blocks: ceil(50000/256)

// ---------------- scratch (device globals; zero-initialized at load) --------
// INVARIANT: g_ncnt is ZERO on entry to every kernel_launch call: statically
// zero-initialized for the first call, re-zeroed by k_zero_ncnt on the side
// stream AFTER k_scanC (its last reader) each call.
// g_pool is zeroed at the START of each call by k_prep (written only later).
__device__ float g_dis[NN];
__device__ float g_h  [(size_t)NN * DH];    // h * dis (pre-scaled!)
__device__ float g_agg[(size_t)NN * DH];
__device__ float g_pool[GG * DH];
__device__ __nv_bfloat16 g_W1h[DIN * DH], g_W1l[DIN * DH];
__device__ __nv_bfloat16 g_W2h[DH * DH],  g_W2l[DH * DH];
// CSR scratch
__device__ int      g_ncnt[NN];
__device__ int      g_tmp [NN];
__device__ int      g_bsum[256];
__device__ int      g_noff[NN + 1];
__device__ int      g_ncur[NN];
__device__ unsigned g_esrc[EE];      // src ids sorted by dst

// ---------------- prep: weight split + degree count + pool zero -------------
__global__ void __launch_bounds__(256)
k_prep(const float* __restrict__ W1, const float* __restrict__ W2,
       const int* __restrict__ dst)
{
    int i = blockIdx.x * blockDim.x + threadIdx.x;
    if (i < DIN * DH) {
        float f = W1[i];
        __nv_bfloat16 hi = __float2bfloat16(f);
        g_W1h[i] = hi;
        g_W1l[i] = __float2bfloat16(f - __bfloat162float(hi));
    }
    if (i < DH * DH) {
        float f = W2[i];
        __nv_bfloat16 hi = __float2bfloat16(f);
        g_W2h[i] = hi;
        g_W2l[i] = __float2bfloat16(f - __bfloat162float(hi));
    }
    if (i < GG * DH) g_pool[i] = 0.0f;           // pool written only later
    if (i < EE) atomicAdd(&g_ncnt[dst[i]], 1);   // g_ncnt zero on entry
}

// ---------------- scan (dis fused into C) ------------------------------------
__global__ void __launch_bounds__(256) k_scanA() {
    __shared__ int sh[256];
    int t  = threadIdx.x;
    int gi = blockIdx.x * 256 + t;
    int v  = (gi < NN) ? g_ncnt[gi] : 0;
    sh[t] = v; __syncthreads();
#pragma unroll
    for (int off = 1; off < 256; off <<= 1) {
        int u = (t >= off) ? sh[t - off] : 0;
        __syncthreads();
        sh[t] += u;
        __syncthreads();
    }
    if (gi < NN) g_tmp[gi] = sh[t];                   // inclusive within block
    if (t == 255) g_bsum[blockIdx.x] = sh[255];
}
__global__ void __launch_bounds__(256) k_scanC() {
    __shared__ int sb[256];
    int t = threadIdx.x;
    sb[t] = (t < SCB) ? g_bsum[t] : 0;
    __syncthreads();
#pragma unroll
    for (int off = 1; off < 256; off <<= 1) {
        int u = (t >= off) ? sb[t - off] : 0;
        __syncthreads();
        sb[t] += u;
        __syncthreads();
    }
    int gi = blockIdx.x * 256 + t;
    if (gi >= NN) return;
    int base = (blockIdx.x > 0) ? sb[blockIdx.x - 1] : 0;
    int cnt  = g_ncnt[gi];
    int inc  = g_tmp[gi] + base;
    g_noff[gi + 1] = inc;
    g_ncur[gi]     = inc - cnt;
    g_dis[gi]      = rsqrtf(1.0f + (float)cnt);       // fused deg_finish
    if (gi == 0) g_noff[0] = 0;
}
__global__ void __launch_bounds__(256)
k_reorder(const int* __restrict__ src, const int* __restrict__ dst) {
    int e = blockIdx.x * blockDim.x + threadIdx.x;
    if (e >= EE) return;
    int pos = atomicAdd(&g_ncur[dst[e]], 1);
    g_esrc[pos] = (unsigned)src[e];
}
__global__ void __launch_bounds__(256) k_zero_ncnt() {
    int i = blockIdx.x * blockDim.x + threadIdx.x;
    if (i < NN) g_ncnt[i] = 0;            // for the NEXT call's k_prep
}

// ---------------- mma / cp.async helpers --------------------------------------
__device__ __forceinline__ unsigned smem_u32(const void* p) {
    return (unsigned)__cvta_generic_to_shared(p);
}
#define LDSM_X4(r, addr) \
    asm volatile("ldmatrix.sync.aligned.m8n8.x4.shared.b16 {%0,%1,%2,%3},[%4];" \
                 : "=r"((r)[0]), "=r"((r)[1]), "=r"((r)[2]), "=r"((r)[3]) : "r"(addr))
#define LDSM_X2_T(r, addr) \
    asm volatile("ldmatrix.sync.aligned.m8n8.x2.trans.shared.b16 {%0,%1},[%2];" \
                 : "=r"((r)[0]), "=r"((r)[1]) : "r"(addr))
#define MMA_BF16(d, a, b) \
    asm volatile("mma.sync.aligned.m16n8k16.row.col.f32.bf16.bf16.f32 " \
                 "{%0,%1,%2,%3},{%4,%5,%6,%7},{%8,%9},{%0,%1,%2,%3};" \
                 : "+f"((d)[0]), "+f"((d)[1]), "+f"((d)[2]), "+f"((d)[3]) \
                 : "r"((a)[0]), "r"((a)[1]), "r"((a)[2]), "r"((a)[3]), \
                   "r"((b)[0]), "r"((b)[1]))
#define CP_ASYNC16(dst, src, sz) \
    asm volatile("cp.async.cg.shared.global [%0], [%1], 16, %2;" \
                 :: "r"(dst), "l"(src), "r"(sz) : "memory")
#define CP_COMMIT() asm volatile("cp.async.commit_group;" ::: "memory")
#define CP_WAIT2()  asm volatile("cp.async.wait_group 2;" ::: "memory")

// dynamic smem layout (bytes)
#define XS_OFF   0                       // float Xs[3][128*16]   = 24576
#define AH_OFF   24576                   // bf16  Ah[2][128*24]   = 12288
#define AL_OFF   36864                   // bf16  Al[2][128*24]   = 12288
#define BH_OFF   49152                   // bf16  Bh[2][16*104]   =  6656
#define BL_OFF   55808                   // bf16  Bl[2][16*104]   =  6656
#define BS_OFF   62464                   // float bs[96]          =   384
#define SMEM_TOT 62848

// ---------------- cp.async-pipelined bf16-split tensor GEMM -----------------
// (R14-proven form.) Epilogue: g_h = acc*dis; g_agg = acc*dis^2.
template <int K, bool RELU_BIAS, bool IN_IS_AGG, int WSEL>
__global__ void __launch_bounds__(256, 2)
k_gemm(const float* __restrict__ in, const float* __restrict__ bias)
{
    extern __shared__ char smem_raw[];
    float*         Xs = (float*)(smem_raw + XS_OFF);          // [3][2048]
    __nv_bfloat16* Ah = (__nv_bfloat16*)(smem_raw + AH_OFF);  // [2][3072]
    __nv_bfloat16* Al = (__nv_bfloat16*)(smem_raw + AL_OFF);
    __nv_bfloat16* Bh = (__nv_bfloat16*)(smem_raw + BH_OFF);  // [2][1664]
    __nv_bfloat16* Bl = (__nv_bfloat16*)(smem_raw + BL_OFF);
    float*         bs = (float*)(smem_raw + BS_OFF);

    const int tid  = threadIdx.x;
    const int lane = tid & 31;
    const int wid  = tid >> 5;
    const int wm   = wid & 3;
    const int wn   = wid >> 2;
    const int r0   = blockIdx.x * 128;
    const int gidx = lane >> 2;
    const int tidx = lane & 3;

    const float* __restrict__ src_in = IN_IS_AGG ? (const float*)g_agg : in;
    const uint4* __restrict__ Wh4 =
        (const uint4*)(WSEL == 1 ? (const void*)g_W1h : (const void*)g_W2h);
    const uint4* __restrict__ Wl4 =
        (const uint4*)(WSEL == 1 ? (const void*)g_W1l : (const void*)g_W2l);

    if (RELU_BIAS) { if (tid < DH) bs[tid] = bias[tid]; }

    float acc[2][6][4];
#pragma unroll
    for (int mt = 0; mt < 2; mt++)
#pragma unroll
        for (int nt = 0; nt < 6; nt++)
#pragma unroll
            for (int q = 0; q < 4; q++) acc[mt][nt][q] = 0.0f;

    unsigned a_h0[2], a_l0[2];
#pragma unroll
    for (int mt = 0; mt < 2; mt++) {
        int row = wm * 32 + mt * 16 + (lane & 15);
        int col = (lane >> 4) * 8;
        a_h0[mt] = smem_u32(&Ah[row * 24 + col]);
        a_l0[mt] = smem_u32(&Al[row * 24 + col]);
    }
    unsigned b_h0[6], b_l0[6];
#pragma unroll
    for (int nt = 0; nt < 6; nt++) {
        int krow  = lane & 15;
        int cbase = wn * 48 + nt * 8;
        b_h0[nt] = smem_u32(&Bh[krow * 104 + cbase]);
        b_l0[nt] = smem_u32(&Bl[krow * 104 + cbase]);
    }
    const unsigned A_STRIDE = 128 * 24 * 2;   // bytes per Ah/Al buffer
    const unsigned B_STRIDE = 16 * 104 * 2;   // bytes per Bh/Bl buffer
    const unsigned xs_u32   = smem_u32(Xs);

    auto issue_x = [&](int stage) {
        const int k0 = stage * 16;
        const unsigned xb = (unsigned)(stage % 3);
#pragma unroll
        for (int t = 0; t < 2; t++) {
            int idx = tid + t * 256;
            int row = idx >> 2, q = idx & 3;
            int gr = r0 + row, gk = k0 + q * 4;
            const float* src = src_in + (size_t)gr * K + gk;
            int sz = (gr < NN && gk + 4 <= K) ? 16 : 0;
            if (sz == 0) src = src_in;                 // keep address valid
            CP_ASYNC16(xs_u32 + xb * 8192u + (unsigned)idx * 16u, src, sz);
        }
    };

    uint4 pb[2];
    auto load_pb = [&](int stage) {
        const int k0 = stage * 16;
#pragma unroll
        for (int t = 0; t < 2; t++) {
            int idx = tid + t * 256;
            if (idx < 384) {
                int half = (idx >= 192);
                int j  = idx - half * 192;
                int kk = j / 12, c = j % 12;
                int gk = k0 + kk;
                pb[t] = make_uint4(0u, 0u, 0u, 0u);
                if (gk < K)
                    pb[t] = (half ? Wl4 : Wh4)[gk * 12 + c];
            }
        }
    };

    const int nstage = (K + 15) / 16;    // 19 or 6; always >= 4
    issue_x(0); CP_COMMIT();
    issue_x(1); CP_COMMIT();
    issue_x(2); CP_COMMIT();
    load_pb(0);
    __syncthreads();                     // bs visible before first convert

    for (int s = 0; s < nstage; s++) {
        const int buf = s & 1;
        const int xb  = s % 3;
        CP_WAIT2();                      // my stage-s Xs chunks arrived
        {
            const float* xsrc = Xs + xb * 2048;
#pragma unroll
            for (int t = 0; t < 2; t++) {
                int idx = tid + t * 256;
                int row = idx >> 2, q = idx & 3;
                float4 v = *reinterpret_cast<const float4*>(xsrc + idx * 4);
                float e[4] = {v.x, v.y, v.z, v.w};
                unsigned hp[2], lp[2];
#pragma unroll
                for (int p = 0; p < 2; p++) {
                    float f0 = e[p * 2], f1 = e[p * 2 + 1];
                    if (RELU_BIAS) {
                        int gk = s * 16 + q * 4 + p * 2;
                        f0 = fmaxf(f0 + bs[gk], 0.0f);
                        f1 = fmaxf(f1 + bs[gk + 1], 0.0f);
                    }
                    __nv_bfloat162 h2 = make_bfloat162(__float2bfloat16(f0),
                                                       __float2bfloat16(f1));
                    __nv_bfloat162 l2 = make_bfloat162(
                        __float2bfloat16(f0 - __bfloat162float(h2.x)),
                        __float2bfloat16(f1 - __bfloat162float(h2.y)));
                    hp[p] = *reinterpret_cast<unsigned*>(&h2);
                    lp[p] = *reinterpret_cast<unsigned*>(&l2);
                }
                *reinterpret_cast<uint2*>(&Ah[buf * 3072 + row * 24 + q * 4]) =
                    make_uint2(hp[0], hp[1]);
                *reinterpret_cast<uint2*>(&Al[buf * 3072 + row * 24 + q * 4]) =
                    make_uint2(lp[0], lp[1]);
            }
        }
        if (s + 3 < nstage) issue_x(s + 3);   // reuse Xs[xb]
        CP_COMMIT();                          // exactly one group per iteration
#pragma unroll
        for (int t = 0; t < 2; t++) {
            int idx = tid + t * 256;
            if (idx < 384) {
                int half = (idx >= 192);
                int j  = idx - half * 192;
                int kk = j / 12, c = j % 12;
                __nv_bfloat16* dstp = (half ? Bl : Bh) + buf * 1664;
                *reinterpret_cast<uint4*>(&dstp[kk * 104 + c * 8]) = pb[t];
            }
        }
        __syncthreads();
        if (s + 1 < nstage) load_pb(s + 1);

        const unsigned ao = buf * A_STRIDE, bo = buf * B_STRIDE;
        unsigned ah[2][4], al[2][4], bh[6][2], bl[6][2];
#pragma unroll
        for (int mt = 0; mt < 2; mt++) {
            LDSM_X4(ah[mt], a_h0[mt] + ao);
            LDSM_X4(al[mt], a_l0[mt] + ao);
        }
#pragma unroll
        for (int nt = 0; nt < 6; nt++) {
            LDSM_X2_T(bh[nt], b_h0[nt] + bo);
            LDSM_X2_T(bl[nt], b_l0[nt] + bo);
        }
#pragma unroll
        for (int mt = 0; mt < 2; mt++)
#pragma unroll
            for (int nt = 0; nt < 6; nt++) {
                MMA_BF16(acc[mt][nt], ah[mt], bh[nt]);
                MMA_BF16(acc[mt][nt], ah[mt], bl[nt]);
                MMA_BF16(acc[mt][nt], al[mt], bh[nt]);
            }
    }

#pragma unroll
    for (int mt = 0; mt < 2; mt++) {
        int rbase = r0 + wm * 32 + mt * 16 + gidx;
#pragma unroll
        for (int half = 0; half < 2; half++) {
            int r = rbase + half * 8;
            if (r >= NN) continue;
            float ds = g_dis[r];
            float d2 = ds * ds;
#pragma unroll
            for (int nt = 0; nt < 6; nt++) {
                int c = wn * 48 + nt * 8 + tidx * 2;
                float v0 = acc[mt][nt][half * 2 + 0];
                float v1 = acc[mt][nt][half * 2 + 1];
                size_t o = (size_t)r * 96 + c;
                *reinterpret_cast<float2*>(g_h + o)   = make_float2(v0 * ds, v1 * ds);
                *reinterpret_cast<float2*>(g_agg + o) = make_float2(v0 * d2, v1 * d2);
            }
        }
    }
}

// ---------------- CSR scatter: one warp per dst node -------------------------
// FINAL=false: g_agg[w] += sum * dis[w]  (layer 1)
// FINAL=true : pooling fused with block-level run-length aggregation.
// NOTE: NN = 50000 = 6250 blocks * 8 warps exactly -> no partial blocks.
template <bool FINAL>
__global__ void __launch_bounds__(256)
k_scatter_csr(const float* __restrict__ b2, const int* __restrict__ batch)
{
    int w    = (blockIdx.x * 256 + threadIdx.x) >> 5;   // node id
    int lane = threadIdx.x & 31;
    int wb   = (threadIdx.x >> 5);                      // warp within block
    if (!FINAL && w >= NN) return;

    const int beg = g_noff[w], end = g_noff[w + 1];

    float a0 = 0.f, a1 = 0.f, a2 = 0.f;
    int e = beg;
    for (; e + 4 <= end; e += 4) {
        unsigned s0 = g_esrc[e],     s1 = g_esrc[e + 1];
        unsigned s2 = g_esrc[e + 2], s3 = g_esrc[e + 3];
        const float* r0 = g_h + (size_t)s0 * 96;
        const float* r1 = g_h + (size_t)s1 * 96;
        const float* r2 = g_h + (size_t)s2 * 96;
        const float* r3 = g_h + (size_t)s3 * 96;
        float v00 = r0[lane], v01 = r0[lane + 32], v02 = r0[lane + 64];
        float v10 = r1[lane], v11 = r1[lane + 32], v12 = r1[lane + 64];
        float v20 = r2[lane], v21 = r2[lane + 32], v22 = r2[lane + 64];
        float v30 = r3[lane], v31 = r3[lane + 32], v32 = r3[lane + 64];
        a0 += (v00 + v10) + (v20 + v30);
        a1 += (v01 + v11) + (v21 + v31);
        a2 += (v02 + v12) + (v22 + v32);
    }
    for (; e < end; e++) {
        const float* r = g_h + (size_t)g_esrc[e] * 96;
        a0 += r[lane]; a1 += r[lane + 32]; a2 += r[lane + 64];
    }
    float dw = g_dis[w];
    if (!FINAL) {
        float* o = g_agg + (size_t)w * 96;
        o[lane]      += a0 * dw;
        o[lane + 32] += a1 * dw;
        o[lane + 64] += a2 * dw;
    } else {
        __shared__ float sp[8][96];
        __shared__ int   sg[8];
        const float* o = g_agg + (size_t)w * 96;
        sp[wb][lane]      = fmaxf(o[lane]      + a0 * dw + b2[lane],      0.0f);
        sp[wb][lane + 32] = fmaxf(o[lane + 32] + a1 * dw + b2[lane + 32], 0.0f);
        sp[wb][lane + 64] = fmaxf(o[lane + 64] + a2 * dw + b2[lane + 64], 0.0f);
        if (lane == 0) sg[wb] = batch[w];
        __syncthreads();
        int c = threadIdx.x;
        if (c < 96) {
            float acc = sp[0][c];
            int   cur = sg[0];
#pragma unroll
            for (int j = 1; j < 8; j++) {
                int gj = sg[j];
                if (gj != cur) {
                    atomicAdd(&g_pool[cur * DH + c], acc);
                    acc = 0.0f; cur = gj;
                }
                acc += sp[j][c];
            }
            atomicAdd(&g_pool[cur * DH + c], acc);
        }
    }
}

// ---------------- head (counts via binary search on sorted batch) ------------
__global__ void k_fc(const float* __restrict__ Wfc, const float* __restrict__ bfc,
                     const int* __restrict__ batch, float* __restrict__ out)
{
    int t = threadIdx.x;
    if (t >= GG * DOUT) return;
    int g = t >> 1, o = t & 1;
    int lo = 0, hi = NN;
    while (lo < hi) { int m = (lo + hi) >> 1; if (batch[m] < g) lo = m + 1; else hi = m; }
    int lb = lo;
    lo = 0; hi = NN;
    while (lo < hi) { int m = (lo + hi) >> 1; if (batch[m] <= g) lo = m + 1; else hi = m; }
    float cn = fmaxf((float)(lo - lb), 1.0f);
    float s = bfc[o];
    for (int c = 0; c < DH; c++)
        s += (g_pool[g * DH + c] / cn) * Wfc[c * DOUT + o];
    out[g * DOUT + o] = s;
}

// ---------------- launch ------------------------------------------------------
extern "C" void kernel_launch(void* const* d_in, const int* in_sizes, int n_in,
                              void* d_out, int out_size)
{
    const float* x    = (const float*)d_in[0];
    const float* W1   = (const float*)d_in[1];
    const float* b1   = (const float*)d_in[2];
    const float* W2   = (const float*)d_in[3];
    const float* b2   = (const float*)d_in[4];
    const float* Wfc  = (const float*)d_in[5];
    const float* bfc  = (const float*)d_in[6];
    const int*   src  = (const int*)d_in[7];
    const int*   dst  = (const int*)d_in[8];
    const int*   batch= (const int*)d_in[9];
    float* out = (float*)d_out;

    const int nb_e = (EE + 255) / 256;
    const int nb_g = (NN + 127) / 128;
    const int nb_s = (NN * 32 + 255) / 256;   // one warp per node (6250, exact)

    // host-side handles, created once (no device memory involved)
    static cudaStream_t s_side = nullptr;
    static cudaEvent_t  ev_fork = nullptr, ev_join = nullptr;
    if (s_side == nullptr) {
        cudaStreamCreateWithFlags(&s_side, cudaStreamNonBlocking);
        cudaEventCreateWithFlags(&ev_fork, cudaEventDisableTiming);
        cudaEventCreateWithFlags(&ev_join, cudaEventDisableTiming);
    }

    cudaFuncSetAttribute(k_gemm<DIN, false, false, 1>,
                         cudaFuncAttributeMaxDynamicSharedMemorySize, SMEM_TOT);
    cudaFuncSetAttribute(k_gemm<DH, true, true, 2>,
                         cudaFuncAttributeMaxDynamicSharedMemorySize, SMEM_TOT);

    k_prep <<<nb_e, 256>>>(W1, W2, dst);      // wsplit + pool zero + deg count
    k_scanA<<<SCB, 256>>>();
    k_scanC<<<SCB, 256>>>();                  // + dis = rsqrt(1+cnt)

    // fork: CSR finalize (reorder + ncnt re-zero) runs concurrently with GEMM1
    cudaEventRecord(ev_fork, 0);
    cudaStreamWaitEvent(s_side, ev_fork, 0);
    k_reorder  <<<nb_e, 256, 0, s_side>>>(src, dst);
    k_zero_ncnt<<<SCB,  256, 0, s_side>>>();
    cudaEventRecord(ev_join, s_side);

    // layer 1 GEMM (needs only weights + dis; independent of reorder)
    k_gemm<DIN, false, false, 1><<<nb_g, 256, SMEM_TOT>>>(x, b1);

    // join: scatter1 needs g_esrc
    cudaStreamWaitEvent(0, ev_join, 0);
    k_scatter_csr<false><<<nb_s, 256>>>(b2, batch);

    // layer 2 (scatter fused with relu+bias+pool, block-aggregated atomics)
    k_gemm<DH, true, true, 2><<<nb_g, 256, SMEM_TOT>>>(nullptr, b1);
    k_scatter_csr<true><<<nb_s, 256>>>(b2, batch);

    k_fc<<<1, 128>>>(Wfc, bfc, batch, out);
}

// round 16
// speedup vs baseline: 1.4821x; 1.0308x over previous
#include <cuda_runtime.h>
#include <cuda_bf16.h>
#include <math.h>

#define NN    50000
#define EE    800000
#define DIN   300
#define DH    96
#define DOUT  2
#define GG    64
#define SCB   196                    // scan blocks: ceil(50000/256)

// ---------------- scratch (device globals; zero-initialized at load) --------
// INVARIANT: g_ncnt is ZERO on entry to every kernel_launch call: statically
// zero-initialized for the first call, re-zeroed by k_zero_ncnt on the side
// stream AFTER its last readers (k_scanC on side, k_dis on main - event edge).
// g_pool is zeroed at the START of each call by k_prep (written only later).
__device__ float g_dis[NN];
__device__ float g_h  [(size_t)NN * DH];    // h * dis (pre-scaled!)
__device__ float g_agg[(size_t)NN * DH];
__device__ float g_pool[GG * DH];
__device__ __nv_bfloat16 g_W1h[DIN * DH], g_W1l[DIN * DH];
__device__ __nv_bfloat16 g_W2h[DH * DH],  g_W2l[DH * DH];
// CSR scratch
__device__ int      g_ncnt[NN];
__device__ int      g_tmp [NN];
__device__ int      g_bsum[256];
__device__ int      g_noff[NN + 1];
__device__ int      g_ncur[NN];
__device__ unsigned g_esrc[EE];      // src ids sorted by dst

// ---------------- prep: weight split + degree count + pool zero -------------
__global__ void __launch_bounds__(256)
k_prep(const float* __restrict__ W1, const float* __restrict__ W2,
       const int* __restrict__ dst)
{
    int i = blockIdx.x * blockDim.x + threadIdx.x;
    if (i < DIN * DH) {
        float f = W1[i];
        __nv_bfloat16 hi = __float2bfloat16(f);
        g_W1h[i] = hi;
        g_W1l[i] = __float2bfloat16(f - __bfloat162float(hi));
    }
    if (i < DH * DH) {
        float f = W2[i];
        __nv_bfloat16 hi = __float2bfloat16(f);
        g_W2h[i] = hi;
        g_W2l[i] = __float2bfloat16(f - __bfloat162float(hi));
    }
    if (i < GG * DH) g_pool[i] = 0.0f;           // pool written only later
    if (i < EE) atomicAdd(&g_ncnt[dst[i]], 1);   // g_ncnt zero on entry
}

// ---------------- dis = rsqrt(1 + deg)  (main stream; feeds GEMM1) ----------
__global__ void __launch_bounds__(256) k_dis() {
    int i = blockIdx.x * blockDim.x + threadIdx.x;
    if (i < NN) g_dis[i] = rsqrtf(1.0f + (float)g_ncnt[i]);
}

// ---------------- scan (side stream; offsets only) ----------------------------
__global__ void __launch_bounds__(256) k_scanA() {
    __shared__ int sh[256];
    int t  = threadIdx.x;
    int gi = blockIdx.x * 256 + t;
    int v  = (gi < NN) ? g_ncnt[gi] : 0;
    sh[t] = v; __syncthreads();
#pragma unroll
    for (int off = 1; off < 256; off <<= 1) {
        int u = (t >= off) ? sh[t - off] : 0;
        __syncthreads();
        sh[t] += u;
        __syncthreads();
    }
    if (gi < NN) g_tmp[gi] = sh[t];                   // inclusive within block
    if (t == 255) g_bsum[blockIdx.x] = sh[255];
}
__global__ void __launch_bounds__(256) k_scanC() {
    __shared__ int sb[256];
    int t = threadIdx.x;
    sb[t] = (t < SCB) ? g_bsum[t] : 0;
    __syncthreads();
#pragma unroll
    for (int off = 1; off < 256; off <<= 1) {
        int u = (t >= off) ? sb[t - off] : 0;
        __syncthreads();
        sb[t] += u;
        __syncthreads();
    }
    int gi = blockIdx.x * 256 + t;
    if (gi >= NN) return;
    int base = (blockIdx.x > 0) ? sb[blockIdx.x - 1] : 0;
    int cnt  = g_ncnt[gi];
    int inc  = g_tmp[gi] + base;
    g_noff[gi + 1] = inc;
    g_ncur[gi]     = inc - cnt;
    if (gi == 0) g_noff[0] = 0;
}
__global__ void __launch_bounds__(256)
k_reorder(const int* __restrict__ src, const int* __restrict__ dst) {
    int e = blockIdx.x * blockDim.x + threadIdx.x;
    if (e >= EE) return;
    int pos = atomicAdd(&g_ncur[dst[e]], 1);
    g_esrc[pos] = (unsigned)src[e];
}
__global__ void __launch_bounds__(256) k_zero_ncnt() {
    int i = blockIdx.x * blockDim.x + threadIdx.x;
    if (i < NN) g_ncnt[i] = 0;            // for the NEXT call's k_prep
}

// ---------------- mma / cp.async helpers --------------------------------------
__device__ __forceinline__ unsigned smem_u32(const void* p) {
    return (unsigned)__cvta_generic_to_shared(p);
}
#define LDSM_X4(r, addr) \
    asm volatile("ldmatrix.sync.aligned.m8n8.x4.shared.b16 {%0,%1,%2,%3},[%4];" \
                 : "=r"((r)[0]), "=r"((r)[1]), "=r"((r)[2]), "=r"((r)[3]) : "r"(addr))
#define LDSM_X2_T(r, addr) \
    asm volatile("ldmatrix.sync.aligned.m8n8.x2.trans.shared.b16 {%0,%1},[%2];" \
                 : "=r"((r)[0]), "=r"((r)[1]) : "r"(addr))
#define MMA_BF16(d, a, b) \
    asm volatile("mma.sync.aligned.m16n8k16.row.col.f32.bf16.bf16.f32 " \
                 "{%0,%1,%2,%3},{%4,%5,%6,%7},{%8,%9},{%0,%1,%2,%3};" \
                 : "+f"((d)[0]), "+f"((d)[1]), "+f"((d)[2]), "+f"((d)[3]) \
                 : "r"((a)[0]), "r"((a)[1]), "r"((a)[2]), "r"((a)[3]), \
                   "r"((b)[0]), "r"((b)[1]))
#define CP_ASYNC16(dst, src, sz) \
    asm volatile("cp.async.cg.shared.global [%0], [%1], 16, %2;" \
                 :: "r"(dst), "l"(src), "r"(sz) : "memory")
#define CP_COMMIT() asm volatile("cp.async.commit_group;" ::: "memory")
#define CP_WAIT2()  asm volatile("cp.async.wait_group 2;" ::: "memory")

// dynamic smem layout (bytes)
#define XS_OFF   0                       // float Xs[3][128*16]   = 24576
#define AH_OFF   24576                   // bf16  Ah[2][128*24]   = 12288
#define AL_OFF   36864                   // bf16  Al[2][128*24]   = 12288
#define BH_OFF   49152                   // bf16  Bh[2][16*104]   =  6656
#define BL_OFF   55808                   // bf16  Bl[2][16*104]   =  6656
#define BS_OFF   62464                   // float bs[96]          =   384
#define SMEM_TOT 62848

// ---------------- cp.async-pipelined bf16-split tensor GEMM -----------------
// (R14-proven form.) Epilogue: g_h = acc*dis; g_agg = acc*dis^2.
template <int K, bool RELU_BIAS, bool IN_IS_AGG, int WSEL>
__global__ void __launch_bounds__(256, 2)
k_gemm(const float* __restrict__ in, const float* __restrict__ bias)
{
    extern __shared__ char smem_raw[];
    float*         Xs = (float*)(smem_raw + XS_OFF);          // [3][2048]
    __nv_bfloat16* Ah = (__nv_bfloat16*)(smem_raw + AH_OFF);  // [2][3072]
    __nv_bfloat16* Al = (__nv_bfloat16*)(smem_raw + AL_OFF);
    __nv_bfloat16* Bh = (__nv_bfloat16*)(smem_raw + BH_OFF);  // [2][1664]
    __nv_bfloat16* Bl = (__nv_bfloat16*)(smem_raw + BL_OFF);
    float*         bs = (float*)(smem_raw + BS_OFF);

    const int tid  = threadIdx.x;
    const int lane = tid & 31;
    const int wid  = tid >> 5;
    const int wm   = wid & 3;
    const int wn   = wid >> 2;
    const int r0   = blockIdx.x * 128;
    const int gidx = lane >> 2;
    const int tidx = lane & 3;

    const float* __restrict__ src_in = IN_IS_AGG ? (const float*)g_agg : in;
    const uint4* __restrict__ Wh4 =
        (const uint4*)(WSEL == 1 ? (const void*)g_W1h : (const void*)g_W2h);
    const uint4* __restrict__ Wl4 =
        (const uint4*)(WSEL == 1 ? (const void*)g_W1l : (const void*)g_W2l);

    if (RELU_BIAS) { if (tid < DH) bs[tid] = bias[tid]; }

    float acc[2][6][4];
#pragma unroll
    for (int mt = 0; mt < 2; mt++)
#pragma unroll
        for (int nt = 0; nt < 6; nt++)
#pragma unroll
            for (int q = 0; q < 4; q++) acc[mt][nt][q] = 0.0f;

    unsigned a_h0[2], a_l0[2];
#pragma unroll
    for (int mt = 0; mt < 2; mt++) {
        int row = wm * 32 + mt * 16 + (lane & 15);
        int col = (lane >> 4) * 8;
        a_h0[mt] = smem_u32(&Ah[row * 24 + col]);
        a_l0[mt] = smem_u32(&Al[row * 24 + col]);
    }
    unsigned b_h0[6], b_l0[6];
#pragma unroll
    for (int nt = 0; nt < 6; nt++) {
        int krow  = lane & 15;
        int cbase = wn * 48 + nt * 8;
        b_h0[nt] = smem_u32(&Bh[krow * 104 + cbase]);
        b_l0[nt] = smem_u32(&Bl[krow * 104 + cbase]);
    }
    const unsigned A_STRIDE = 128 * 24 * 2;   // bytes per Ah/Al buffer
    const unsigned B_STRIDE = 16 * 104 * 2;   // bytes per Bh/Bl buffer
    const unsigned xs_u32   = smem_u32(Xs);

    auto issue_x = [&](int stage) {
        const int k0 = stage * 16;
        const unsigned xb = (unsigned)(stage % 3);
#pragma unroll
        for (int t = 0; t < 2; t++) {
            int idx = tid + t * 256;
            int row = idx >> 2, q = idx & 3;
            int gr = r0 + row, gk = k0 + q * 4;
            const float* src = src_in + (size_t)gr * K + gk;
            int sz = (gr < NN && gk + 4 <= K) ? 16 : 0;
            if (sz == 0) src = src_in;                 // keep address valid
            CP_ASYNC16(xs_u32 + xb * 8192u + (unsigned)idx * 16u, src, sz);
        }
    };

    uint4 pb[2];
    auto load_pb = [&](int stage) {
        const int k0 = stage * 16;
#pragma unroll
        for (int t = 0; t < 2; t++) {
            int idx = tid + t * 256;
            if (idx < 384) {
                int half = (idx >= 192);
                int j  = idx - half * 192;
                int kk = j / 12, c = j % 12;
                int gk = k0 + kk;
                pb[t] = make_uint4(0u, 0u, 0u, 0u);
                if (gk < K)
                    pb[t] = (half ? Wl4 : Wh4)[gk * 12 + c];
            }
        }
    };

    const int nstage = (K + 15) / 16;    // 19 or 6; always >= 4
    issue_x(0); CP_COMMIT();
    issue_x(1); CP_COMMIT();
    issue_x(2); CP_COMMIT();
    load_pb(0);
    __syncthreads();                     // bs visible before first convert

    for (int s = 0; s < nstage; s++) {
        const int buf = s & 1;
        const int xb  = s % 3;
        CP_WAIT2();                      // my stage-s Xs chunks arrived
        {
            const float* xsrc = Xs + xb * 2048;
#pragma unroll
            for (int t = 0; t < 2; t++) {
                int idx = tid + t * 256;
                int row = idx >> 2, q = idx & 3;
                float4 v = *reinterpret_cast<const float4*>(xsrc + idx * 4);
                float e[4] = {v.x, v.y, v.z, v.w};
                unsigned hp[2], lp[2];
#pragma unroll
                for (int p = 0; p < 2; p++) {
                    float f0 = e[p * 2], f1 = e[p * 2 + 1];
                    if (RELU_BIAS) {
                        int gk = s * 16 + q * 4 + p * 2;
                        f0 = fmaxf(f0 + bs[gk], 0.0f);
                        f1 = fmaxf(f1 + bs[gk + 1], 0.0f);
                    }
                    __nv_bfloat162 h2 = make_bfloat162(__float2bfloat16(f0),
                                                       __float2bfloat16(f1));
                    __nv_bfloat162 l2 = make_bfloat162(
                        __float2bfloat16(f0 - __bfloat162float(h2.x)),
                        __float2bfloat16(f1 - __bfloat162float(h2.y)));
                    hp[p] = *reinterpret_cast<unsigned*>(&h2);
                    lp[p] = *reinterpret_cast<unsigned*>(&l2);
                }
                *reinterpret_cast<uint2*>(&Ah[buf * 3072 + row * 24 + q * 4]) =
                    make_uint2(hp[0], hp[1]);
                *reinterpret_cast<uint2*>(&Al[buf * 3072 + row * 24 + q * 4]) =
                    make_uint2(lp[0], lp[1]);
            }
        }
        if (s + 3 < nstage) issue_x(s + 3);   // reuse Xs[xb]
        CP_COMMIT();                          // exactly one group per iteration
#pragma unroll
        for (int t = 0; t < 2; t++) {
            int idx = tid + t * 256;
            if (idx < 384) {
                int half = (idx >= 192);
                int j  = idx - half * 192;
                int kk = j / 12, c = j % 12;
                __nv_bfloat16* dstp = (half ? Bl : Bh) + buf * 1664;
                *reinterpret_cast<uint4*>(&dstp[kk * 104 + c * 8]) = pb[t];
            }
        }
        __syncthreads();
        if (s + 1 < nstage) load_pb(s + 1);

        const unsigned ao = buf * A_STRIDE, bo = buf * B_STRIDE;
        unsigned ah[2][4], al[2][4], bh[6][2], bl[6][2];
#pragma unroll
        for (int mt = 0; mt < 2; mt++) {
            LDSM_X4(ah[mt], a_h0[mt] + ao);
            LDSM_X4(al[mt], a_l0[mt] + ao);
        }
#pragma unroll
        for (int nt = 0; nt < 6; nt++) {
            LDSM_X2_T(bh[nt], b_h0[nt] + bo);
            LDSM_X2_T(bl[nt], b_l0[nt] + bo);
        }
#pragma unroll
        for (int mt = 0; mt < 2; mt++)
#pragma unroll
            for (int nt = 0; nt < 6; nt++) {
                MMA_BF16(acc[mt][nt], ah[mt], bh[nt]);
                MMA_BF16(acc[mt][nt], ah[mt], bl[nt]);
                MMA_BF16(acc[mt][nt], al[mt], bh[nt]);
            }
    }

#pragma unroll
    for (int mt = 0; mt < 2; mt++) {
        int rbase = r0 + wm * 32 + mt * 16 + gidx;
#pragma unroll
        for (int half = 0; half < 2; half++) {
            int r = rbase + half * 8;
            if (r >= NN) continue;
            float ds = g_dis[r];
            float d2 = ds * ds;
#pragma unroll
            for (int nt = 0; nt < 6; nt++) {
                int c = wn * 48 + nt * 8 + tidx * 2;
                float v0 = acc[mt][nt][half * 2 + 0];
                float v1 = acc[mt][nt][half * 2 + 1];
                size_t o = (size_t)r * 96 + c;
                *reinterpret_cast<float2*>(g_h + o)   = make_float2(v0 * ds, v1 * ds);
                *reinterpret_cast<float2*>(g_agg + o) = make_float2(v0 * d2, v1 * d2);
            }
        }
    }
}

// ---------------- CSR scatter: one warp per dst node -------------------------
// FINAL=false: g_agg[w] += sum * dis[w]  (layer 1)
// FINAL=true : pooling fused with block-level run-length aggregation.
// NOTE: NN = 50000 = 6250 blocks * 8 warps exactly -> no partial blocks.
template <bool FINAL>
__global__ void __launch_bounds__(256)
k_scatter_csr(const float* __restrict__ b2, const int* __restrict__ batch)
{
    int w    = (blockIdx.x * 256 + threadIdx.x) >> 5;   // node id
    int lane = threadIdx.x & 31;
    int wb   = (threadIdx.x >> 5);                      // warp within block
    if (!FINAL && w >= NN) return;

    const int beg = g_noff[w], end = g_noff[w + 1];

    float a0 = 0.f, a1 = 0.f, a2 = 0.f;
    int e = beg;
    for (; e + 4 <= end; e += 4) {
        unsigned s0 = g_esrc[e],     s1 = g_esrc[e + 1];
        unsigned s2 = g_esrc[e + 2], s3 = g_esrc[e + 3];
        const float* r0 = g_h + (size_t)s0 * 96;
        const float* r1 = g_h + (size_t)s1 * 96;
        const float* r2 = g_h + (size_t)s2 * 96;
        const float* r3 = g_h + (size_t)s3 * 96;
        float v00 = r0[lane], v01 = r0[lane + 32], v02 = r0[lane + 64];
        float v10 = r1[lane], v11 = r1[lane + 32], v12 = r1[lane + 64];
        float v20 = r2[lane], v21 = r2[lane + 32], v22 = r2[lane + 64];
        float v30 = r3[lane], v31 = r3[lane + 32], v32 = r3[lane + 64];
        a0 += (v00 + v10) + (v20 + v30);
        a1 += (v01 + v11) + (v21 + v31);
        a2 += (v02 + v12) + (v22 + v32);
    }
    for (; e < end; e++) {
        const float* r = g_h + (size_t)g_esrc[e] * 96;
        a0 += r[lane]; a1 += r[lane + 32]; a2 += r[lane + 64];
    }
    float dw = g_dis[w];
    if (!FINAL) {
        float* o = g_agg + (size_t)w * 96;
        o[lane]      += a0 * dw;
        o[lane + 32] += a1 * dw;
        o[lane + 64] += a2 * dw;
    } else {
        __shared__ float sp[8][96];
        __shared__ int   sg[8];
        const float* o = g_agg + (size_t)w * 96;
        sp[wb][lane]      = fmaxf(o[lane]      + a0 * dw + b2[lane],      0.0f);
        sp[wb][lane + 32] = fmaxf(o[lane + 32] + a1 * dw + b2[lane + 32], 0.0f);
        sp[wb][lane + 64] = fmaxf(o[lane + 64] + a2 * dw + b2[lane + 64], 0.0f);
        if (lane == 0) sg[wb] = batch[w];
        __syncthreads();
        int c = threadIdx.x;
        if (c < 96) {
            float acc = sp[0][c];
            int   cur = sg[0];
#pragma unroll
            for (int j = 1; j < 8; j++) {
                int gj = sg[j];
                if (gj != cur) {
                    atomicAdd(&g_pool[cur * DH + c], acc);
                    acc = 0.0f; cur = gj;
                }
                acc += sp[j][c];
            }
            atomicAdd(&g_pool[cur * DH + c], acc);
        }
    }
}

// ---------------- head (counts via binary search on sorted batch) ------------
__global__ void k_fc(const float* __restrict__ Wfc, const float* __restrict__ bfc,
                     const int* __restrict__ batch, float* __restrict__ out)
{
    int t = threadIdx.x;
    if (t >= GG * DOUT) return;
    int g = t >> 1, o = t & 1;
    int lo = 0, hi = NN;
    while (lo < hi) { int m = (lo + hi) >> 1; if (batch[m] < g) lo = m + 1; else hi = m; }
    int lb = lo;
    lo = 0; hi = NN;
    while (lo < hi) { int m = (lo + hi) >> 1; if (batch[m] <= g) lo = m + 1; else hi = m; }
    float cn = fmaxf((float)(lo - lb), 1.0f);
    float s = bfc[o];
    for (int c = 0; c < DH; c++)
        s += (g_pool[g * DH + c] / cn) * Wfc[c * DOUT + o];
    out[g * DOUT + o] = s;
}

// ---------------- launch ------------------------------------------------------
extern "C" void kernel_launch(void* const* d_in, const int* in_sizes, int n_in,
                              void* d_out, int out_size)
{
    const float* x    = (const float*)d_in[0];
    const float* W1   = (const float*)d_in[1];
    const float* b1   = (const float*)d_in[2];
    const float* W2   = (const float*)d_in[3];
    const float* b2   = (const float*)d_in[4];
    const float* Wfc  = (const float*)d_in[5];
    const float* bfc  = (const float*)d_in[6];
    const int*   src  = (const int*)d_in[7];
    const int*   dst  = (const int*)d_in[8];
    const int*   batch= (const int*)d_in[9];
    float* out = (float*)d_out;

    const int nb_e = (EE + 255) / 256;
    const int nb_g = (NN + 127) / 128;
    const int nb_s = (NN * 32 + 255) / 256;   // one warp per node (6250, exact)

    // host-side handles, created once (no device memory involved)
    static cudaStream_t s_side = nullptr;
    static cudaEvent_t  ev_fork = nullptr, ev_dis = nullptr, ev_join = nullptr;
    if (s_side == nullptr) {
        cudaStreamCreateWithFlags(&s_side, cudaStreamNonBlocking);
        cudaEventCreateWithFlags(&ev_fork, cudaEventDisableTiming);
        cudaEventCreateWithFlags(&ev_dis,  cudaEventDisableTiming);
        cudaEventCreateWithFlags(&ev_join, cudaEventDisableTiming);
    }

    cudaFuncSetAttribute(k_gemm<DIN, false, false, 1>,
                         cudaFuncAttributeMaxDynamicSharedMemorySize, SMEM_TOT);
    cudaFuncSetAttribute(k_gemm<DH, true, true, 2>,
                         cudaFuncAttributeMaxDynamicSharedMemorySize, SMEM_TOT);

    k_prep<<<nb_e, 256>>>(W1, W2, dst);       // wsplit + pool zero + deg count

    // fork: the whole CSR build chain runs concurrently with k_dis + GEMM1
    cudaEventRecord(ev_fork, 0);
    cudaStreamWaitEvent(s_side, ev_fork, 0);
    k_scanA  <<<SCB, 256, 0, s_side>>>();
    k_scanC  <<<SCB, 256, 0, s_side>>>();
    k_reorder<<<nb_e, 256, 0, s_side>>>(src, dst);

    // main: dis (only g_ncnt needed) then GEMM1
    k_dis<<<SCB, 256>>>();
    cudaEventRecord(ev_dis, 0);               // last main-stream g_ncnt reader
    k_gemm<DIN, false, false, 1><<<nb_g, 256, SMEM_TOT>>>(x, b1);

    // side: zero ncnt after BOTH scanC (side order) and k_dis (event edge)
    cudaStreamWaitEvent(s_side, ev_dis, 0);
    k_zero_ncnt<<<SCB, 256, 0, s_side>>>();
    cudaEventRecord(ev_join, s_side);

    // join: scatter1 needs g_noff/g_esrc
    cudaStreamWaitEvent(0, ev_join, 0);
    k_scatter_csr<false><<<nb_s, 256>>>(b2, batch);

    // layer 2 (scatter fused with relu+bias+pool, block-aggregated atomics)
    k_gemm<DH, true, true, 2><<<nb_g, 256, SMEM_TOT>>>(nullptr, b1);
    k_scatter_csr<true><<<nb_s, 256>>>(b2, batch);

    k_fc<<<1, 128>>>(Wfc, bfc, batch, out);
}

// round 17
// speedup vs baseline: 1.5705x; 1.0597x over previous
#include <cuda_runtime.h>
#include <cuda_bf16.h>
#include <cuda_fp16.h>
#include <math.h>

#define NN    50000
#define EE    800000
#define DIN   300
#define DH    96
#define DOUT  2
#define GG    64
#define SCB   196                    // scan blocks: ceil(50000/256)

// ---------------- scratch (device globals; zero-initialized at load) --------
// INVARIANT: g_ncnt is ZERO on entry to every kernel_launch call (re-zeroed on
// the side stream after its last readers). g_pool is zeroed by k_prep.
__device__ float   g_dis[NN];
__device__ __half2 g_h2[(size_t)NN * 48];   // h * dis, fp16 pairs (192 B/row)
__device__ float   g_agg[(size_t)NN * DH];
__device__ float   g_pool[GG * DH];
__device__ __nv_bfloat16 g_W1h[DIN * DH], g_W1l[DIN * DH];
__device__ __nv_bfloat16 g_W2h[DH * DH],  g_W2l[DH * DH];
// CSR scratch
__device__ int      g_ncnt[NN];
__device__ int      g_tmp [NN];
__device__ int      g_bsum[256];
__device__ int      g_noff[NN + 1];
__device__ int      g_ncur[NN];
__device__ unsigned g_esrc[EE];      // src ids sorted by dst

// ---------------- prep: weight split + degree count + pool zero -------------
__global__ void __launch_bounds__(256)
k_prep(const float* __restrict__ W1, const float* __restrict__ W2,
       const int* __restrict__ dst)
{
    int i = blockIdx.x * blockDim.x + threadIdx.x;
    if (i < DIN * DH) {
        float f = W1[i];
        __nv_bfloat16 hi = __float2bfloat16(f);
        g_W1h[i] = hi;
        g_W1l[i] = __float2bfloat16(f - __bfloat162float(hi));
    }
    if (i < DH * DH) {
        float f = W2[i];
        __nv_bfloat16 hi = __float2bfloat16(f);
        g_W2h[i] = hi;
        g_W2l[i] = __float2bfloat16(f - __bfloat162float(hi));
    }
    if (i < GG * DH) g_pool[i] = 0.0f;           // pool written only later
    if (i < EE) atomicAdd(&g_ncnt[dst[i]], 1);   // g_ncnt zero on entry
}

// ---------------- dis = rsqrt(1 + deg)  (main stream; feeds GEMM1) ----------
__global__ void __launch_bounds__(256) k_dis() {
    int i = blockIdx.x * blockDim.x + threadIdx.x;
    if (i < NN) g_dis[i] = rsqrtf(1.0f + (float)g_ncnt[i]);
}

// ---------------- scan (side stream; offsets only) ----------------------------
__global__ void __launch_bounds__(256) k_scanA() {
    __shared__ int sh[256];
    int t  = threadIdx.x;
    int gi = blockIdx.x * 256 + t;
    int v  = (gi < NN) ? g_ncnt[gi] : 0;
    sh[t] = v; __syncthreads();
#pragma unroll
    for (int off = 1; off < 256; off <<= 1) {
        int u = (t >= off) ? sh[t - off] : 0;
        __syncthreads();
        sh[t] += u;
        __syncthreads();
    }
    if (gi < NN) g_tmp[gi] = sh[t];                   // inclusive within block
    if (t == 255) g_bsum[blockIdx.x] = sh[255];
}
__global__ void __launch_bounds__(256) k_scanC() {
    __shared__ int sb[256];
    int t = threadIdx.x;
    sb[t] = (t < SCB) ? g_bsum[t] : 0;
    __syncthreads();
#pragma unroll
    for (int off = 1; off < 256; off <<= 1) {
        int u = (t >= off) ? sb[t - off] : 0;
        __syncthreads();
        sb[t] += u;
        __syncthreads();
    }
    int gi = blockIdx.x * 256 + t;
    if (gi >= NN) return;
    int base = (blockIdx.x > 0) ? sb[blockIdx.x - 1] : 0;
    int cnt  = g_ncnt[gi];
    int inc  = g_tmp[gi] + base;
    g_noff[gi + 1] = inc;
    g_ncur[gi]     = inc - cnt;
    if (gi == 0) g_noff[0] = 0;
}
__global__ void __launch_bounds__(256)
k_reorder(const int* __restrict__ src, const int* __restrict__ dst) {
    int e = blockIdx.x * blockDim.x + threadIdx.x;
    if (e >= EE) return;
    int pos = atomicAdd(&g_ncur[dst[e]], 1);
    g_esrc[pos] = (unsigned)src[e];
}
__global__ void __launch_bounds__(256) k_zero_ncnt() {
    int i = blockIdx.x * blockDim.x + threadIdx.x;
    if (i < NN) g_ncnt[i] = 0;            // for the NEXT call's k_prep
}

// ---------------- mma / cp.async helpers --------------------------------------
__device__ __forceinline__ unsigned smem_u32(const void* p) {
    return (unsigned)__cvta_generic_to_shared(p);
}
#define LDSM_X4(r, addr) \
    asm volatile("ldmatrix.sync.aligned.m8n8.x4.shared.b16 {%0,%1,%2,%3},[%4];" \
                 : "=r"((r)[0]), "=r"((r)[1]), "=r"((r)[2]), "=r"((r)[3]) : "r"(addr))
#define LDSM_X2_T(r, addr) \
    asm volatile("ldmatrix.sync.aligned.m8n8.x2.trans.shared.b16 {%0,%1},[%2];" \
                 : "=r"((r)[0]), "=r"((r)[1]) : "r"(addr))
#define MMA_BF16(d, a, b) \
    asm volatile("mma.sync.aligned.m16n8k16.row.col.f32.bf16.bf16.f32 " \
                 "{%0,%1,%2,%3},{%4,%5,%6,%7},{%8,%9},{%0,%1,%2,%3};" \
                 : "+f"((d)[0]), "+f"((d)[1]), "+f"((d)[2]), "+f"((d)[3]) \
                 : "r"((a)[0]), "r"((a)[1]), "r"((a)[2]), "r"((a)[3]), \
                   "r"((b)[0]), "r"((b)[1]))
#define CP_ASYNC16(dst, src, sz) \
    asm volatile("cp.async.cg.shared.global [%0], [%1], 16, %2;" \
                 :: "r"(dst), "l"(src), "r"(sz) : "memory")
#define CP_COMMIT() asm volatile("cp.async.commit_group;" ::: "memory")
#define CP_WAIT2()  asm volatile("cp.async.wait_group 2;" ::: "memory")

// dynamic smem layout (bytes)
#define XS_OFF   0                       // float Xs[3][128*16]   = 24576
#define AH_OFF   24576                   // bf16  Ah[2][128*24]   = 12288
#define AL_OFF   36864                   // bf16  Al[2][128*24]   = 12288
#define BH_OFF   49152                   // bf16  Bh[2][16*104]   =  6656
#define BL_OFF   55808                   // bf16  Bl[2][16*104]   =  6656
#define BS_OFF   62464                   // float bs[96]          =   384
#define SMEM_TOT 62848

// ---------------- cp.async-pipelined bf16-split tensor GEMM -----------------
// (R14-proven form.) Epilogue: g_h2 = fp16(acc*dis); g_agg = acc*dis^2 (fp32).
template <int K, bool RELU_BIAS, bool IN_IS_AGG, int WSEL>
__global__ void __launch_bounds__(256, 2)
k_gemm(const float* __restrict__ in, const float* __restrict__ bias)
{
    extern __shared__ char smem_raw[];
    float*         Xs = (float*)(smem_raw + XS_OFF);          // [3][2048]
    __nv_bfloat16* Ah = (__nv_bfloat16*)(smem_raw + AH_OFF);  // [2][3072]
    __nv_bfloat16* Al = (__nv_bfloat16*)(smem_raw + AL_OFF);
    __nv_bfloat16* Bh = (__nv_bfloat16*)(smem_raw + BH_OFF);  // [2][1664]
    __nv_bfloat16* Bl = (__nv_bfloat16*)(smem_raw + BL_OFF);
    float*         bs = (float*)(smem_raw + BS_OFF);

    const int tid  = threadIdx.x;
    const int lane = tid & 31;
    const int wid  = tid >> 5;
    const int wm   = wid & 3;
    const int wn   = wid >> 2;
    const int r0   = blockIdx.x * 128;
    const int gidx = lane >> 2;
    const int tidx = lane & 3;

    const float* __restrict__ src_in = IN_IS_AGG ? (const float*)g_agg : in;
    const uint4* __restrict__ Wh4 =
        (const uint4*)(WSEL == 1 ? (const void*)g_W1h : (const void*)g_W2h);
    const uint4* __restrict__ Wl4 =
        (const uint4*)(WSEL == 1 ? (const void*)g_W1l : (const void*)g_W2l);

    if (RELU_BIAS) { if (tid < DH) bs[tid] = bias[tid]; }

    float acc[2][6][4];
#pragma unroll
    for (int mt = 0; mt < 2; mt++)
#pragma unroll
        for (int nt = 0; nt < 6; nt++)
#pragma unroll
            for (int q = 0; q < 4; q++) acc[mt][nt][q] = 0.0f;

    unsigned a_h0[2], a_l0[2];
#pragma unroll
    for (int mt = 0; mt < 2; mt++) {
        int row = wm * 32 + mt * 16 + (lane & 15);
        int col = (lane >> 4) * 8;
        a_h0[mt] = smem_u32(&Ah[row * 24 + col]);
        a_l0[mt] = smem_u32(&Al[row * 24 + col]);
    }
    unsigned b_h0[6], b_l0[6];
#pragma unroll
    for (int nt = 0; nt < 6; nt++) {
        int krow  = lane & 15;
        int cbase = wn * 48 + nt * 8;
        b_h0[nt] = smem_u32(&Bh[krow * 104 + cbase]);
        b_l0[nt] = smem_u32(&Bl[krow * 104 + cbase]);
    }
    const unsigned A_STRIDE = 128 * 24 * 2;   // bytes per Ah/Al buffer
    const unsigned B_STRIDE = 16 * 104 * 2;   // bytes per Bh/Bl buffer
    const unsigned xs_u32   = smem_u32(Xs);

    auto issue_x = [&](int stage) {
        const int k0 = stage * 16;
        const unsigned xb = (unsigned)(stage % 3);
#pragma unroll
        for (int t = 0; t < 2; t++) {
            int idx = tid + t * 256;
            int row = idx >> 2, q = idx & 3;
            int gr = r0 + row, gk = k0 + q * 4;
            const float* src = src_in + (size_t)gr * K + gk;
            int sz = (gr < NN && gk + 4 <= K) ? 16 : 0;
            if (sz == 0) src = src_in;                 // keep address valid
            CP_ASYNC16(xs_u32 + xb * 8192u + (unsigned)idx * 16u, src, sz);
        }
    };

    uint4 pb[2];
    auto load_pb = [&](int stage) {
        const int k0 = stage * 16;
#pragma unroll
        for (int t = 0; t < 2; t++) {
            int idx = tid + t * 256;
            if (idx < 384) {
                int half = (idx >= 192);
                int j  = idx - half * 192;
                int kk = j / 12, c = j % 12;
                int gk = k0 + kk;
                pb[t] = make_uint4(0u, 0u, 0u, 0u);
                if (gk < K)
                    pb[t] = (half ? Wl4 : Wh4)[gk * 12 + c];
            }
        }
    };

    const int nstage = (K + 15) / 16;    // 19 or 6; always >= 4
    issue_x(0); CP_COMMIT();
    issue_x(1); CP_COMMIT();
    issue_x(2); CP_COMMIT();
    load_pb(0);
    __syncthreads();                     // bs visible before first convert

    for (int s = 0; s < nstage; s++) {
        const int buf = s & 1;
        const int xb  = s % 3;
        CP_WAIT2();                      // my stage-s Xs chunks arrived
        {
            const float* xsrc = Xs + xb * 2048;
#pragma unroll
            for (int t = 0; t < 2; t++) {
                int idx = tid + t * 256;
                int row = idx >> 2, q = idx & 3;
                float4 v = *reinterpret_cast<const float4*>(xsrc + idx * 4);
                float e[4] = {v.x, v.y, v.z, v.w};
                unsigned hp[2], lp[2];
#pragma unroll
                for (int p = 0; p < 2; p++) {
                    float f0 = e[p * 2], f1 = e[p * 2 + 1];
                    if (RELU_BIAS) {
                        int gk = s * 16 + q * 4 + p * 2;
                        f0 = fmaxf(f0 + bs[gk], 0.0f);
                        f1 = fmaxf(f1 + bs[gk + 1], 0.0f);
                    }
                    __nv_bfloat162 h2 = make_bfloat162(__float2bfloat16(f0),
                                                       __float2bfloat16(f1));
                    __nv_bfloat162 l2 = make_bfloat162(
                        __float2bfloat16(f0 - __bfloat162float(h2.x)),
                        __float2bfloat16(f1 - __bfloat162float(h2.y)));
                    hp[p] = *reinterpret_cast<unsigned*>(&h2);
                    lp[p] = *reinterpret_cast<unsigned*>(&l2);
                }
                *reinterpret_cast<uint2*>(&Ah[buf * 3072 + row * 24 + q * 4]) =
                    make_uint2(hp[0], hp[1]);
                *reinterpret_cast<uint2*>(&Al[buf * 3072 + row * 24 + q * 4]) =
                    make_uint2(lp[0], lp[1]);
            }
        }
        if (s + 3 < nstage) issue_x(s + 3);   // reuse Xs[xb]
        CP_COMMIT();                          // exactly one group per iteration
#pragma unroll
        for (int t = 0; t < 2; t++) {
            int idx = tid + t * 256;
            if (idx < 384) {
                int half = (idx >= 192);
                int j  = idx - half * 192;
                int kk = j / 12, c = j % 12;
                __nv_bfloat16* dstp = (half ? Bl : Bh) + buf * 1664;
                *reinterpret_cast<uint4*>(&dstp[kk * 104 + c * 8]) = pb[t];
            }
        }
        __syncthreads();
        if (s + 1 < nstage) load_pb(s + 1);

        const unsigned ao = buf * A_STRIDE, bo = buf * B_STRIDE;
        unsigned ah[2][4], al[2][4], bh[6][2], bl[6][2];
#pragma unroll
        for (int mt = 0; mt < 2; mt++) {
            LDSM_X4(ah[mt], a_h0[mt] + ao);
            LDSM_X4(al[mt], a_l0[mt] + ao);
        }
#pragma unroll
        for (int nt = 0; nt < 6; nt++) {
            LDSM_X2_T(bh[nt], b_h0[nt] + bo);
            LDSM_X2_T(bl[nt], b_l0[nt] + bo);
        }
#pragma unroll
        for (int mt = 0; mt < 2; mt++)
#pragma unroll
            for (int nt = 0; nt < 6; nt++) {
                MMA_BF16(acc[mt][nt], ah[mt], bh[nt]);
                MMA_BF16(acc[mt][nt], ah[mt], bl[nt]);
                MMA_BF16(acc[mt][nt], al[mt], bh[nt]);
            }
    }

#pragma unroll
    for (int mt = 0; mt < 2; mt++) {
        int rbase = r0 + wm * 32 + mt * 16 + gidx;
#pragma unroll
        for (int half = 0; half < 2; half++) {
            int r = rbase + half * 8;
            if (r >= NN) continue;
            float ds = g_dis[r];
            float d2 = ds * ds;
#pragma unroll
            for (int nt = 0; nt < 6; nt++) {
                int c = wn * 48 + nt * 8 + tidx * 2;
                float v0 = acc[mt][nt][half * 2 + 0];
                float v1 = acc[mt][nt][half * 2 + 1];
                size_t o = (size_t)r * 96 + c;
                g_h2[(size_t)r * 48 + (c >> 1)] = __floats2half2_rn(v0 * ds, v1 * ds);
                *reinterpret_cast<float2*>(g_agg + o) = make_float2(v0 * d2, v1 * d2);
            }
        }
    }
}

// ---------------- CSR scatter: one warp per dst node, fp16 gather ------------
// Lanes 0-23 each own 4 columns (one uint2 = 2 half2 words) of the 192-byte
// fp16 row. FINAL=false: g_agg[w] += sum*dis[w]. FINAL=true: pooling fused
// with block-level run-length aggregation (batch sorted).
// NOTE: NN = 50000 = 6250 blocks * 8 warps exactly -> no partial blocks.
template <bool FINAL>
__global__ void __launch_bounds__(256)
k_scatter_csr(const float* __restrict__ b2, const int* __restrict__ batch)
{
    int w    = (blockIdx.x * 256 + threadIdx.x) >> 5;   // node id
    int lane = threadIdx.x & 31;
    int wb   = (threadIdx.x >> 5);                      // warp within block
    if (!FINAL && w >= NN) return;

    const int beg = g_noff[w], end = g_noff[w + 1];

    float a0 = 0.f, a1 = 0.f, a2 = 0.f, a3 = 0.f;
    if (lane < 24) {
        int e = beg;
        for (; e + 4 <= end; e += 4) {
            unsigned s0 = g_esrc[e],     s1 = g_esrc[e + 1];
            unsigned s2 = g_esrc[e + 2], s3 = g_esrc[e + 3];
            uint2 u0 = reinterpret_cast<const uint2*>(g_h2 + (size_t)s0 * 48)[lane];
            uint2 u1 = reinterpret_cast<const uint2*>(g_h2 + (size_t)s1 * 48)[lane];
            uint2 u2 = reinterpret_cast<const uint2*>(g_h2 + (size_t)s2 * 48)[lane];
            uint2 u3 = reinterpret_cast<const uint2*>(g_h2 + (size_t)s3 * 48)[lane];
#define ACC4(u) { \
            float2 f0 = __half22float2(*reinterpret_cast<__half2*>(&(u).x)); \
            float2 f1 = __half22float2(*reinterpret_cast<__half2*>(&(u).y)); \
            a0 += f0.x; a1 += f0.y; a2 += f1.x; a3 += f1.y; }
            ACC4(u0) ACC4(u1) ACC4(u2) ACC4(u3)
        }
        for (; e < end; e++) {
            uint2 u = reinterpret_cast<const uint2*>(
                          g_h2 + (size_t)g_esrc[e] * 48)[lane];
            ACC4(u)
        }
#undef ACC4
    }
    float dw = g_dis[w];
    if (!FINAL) {
        if (lane < 24) {
            float4* p = reinterpret_cast<float4*>(g_agg + (size_t)w * 96) + lane;
            float4 cur = *p;
            cur.x += a0 * dw; cur.y += a1 * dw;
            cur.z += a2 * dw; cur.w += a3 * dw;
            *p = cur;
        }
    } else {
        __shared__ alignas(16) float sp[8][96];
        __shared__ int sg[8];
        if (lane < 24) {
            float4 cur = reinterpret_cast<const float4*>(g_agg + (size_t)w * 96)[lane];
            float4 bb  = reinterpret_cast<const float4*>(b2)[lane];
            float4 r;
            r.x = fmaxf(cur.x + a0 * dw + bb.x, 0.0f);
            r.y = fmaxf(cur.y + a1 * dw + bb.y, 0.0f);
            r.z = fmaxf(cur.z + a2 * dw + bb.z, 0.0f);
            r.w = fmaxf(cur.w + a3 * dw + bb.w, 0.0f);
            *reinterpret_cast<float4*>(&sp[wb][lane * 4]) = r;
        }
        if (lane == 0) sg[wb] = batch[w];
        __syncthreads();
        int c = threadIdx.x;
        if (c < 96) {
            float acc = sp[0][c];
            int   cur = sg[0];
#pragma unroll
            for (int j = 1; j < 8; j++) {
                int gj = sg[j];
                if (gj != cur) {
                    atomicAdd(&g_pool[cur * DH + c], acc);
                    acc = 0.0f; cur = gj;
                }
                acc += sp[j][c];
            }
            atomicAdd(&g_pool[cur * DH + c], acc);
        }
    }
}

// ---------------- head (counts via binary search on sorted batch) ------------
__global__ void k_fc(const float* __restrict__ Wfc, const float* __restrict__ bfc,
                     const int* __restrict__ batch, float* __restrict__ out)
{
    int t = threadIdx.x;
    if (t >= GG * DOUT) return;
    int g = t >> 1, o = t & 1;
    int lo = 0, hi = NN;
    while (lo < hi) { int m = (lo + hi) >> 1; if (batch[m] < g) lo = m + 1; else hi = m; }
    int lb = lo;
    lo = 0; hi = NN;
    while (lo < hi) { int m = (lo + hi) >> 1; if (batch[m] <= g) lo = m + 1; else hi = m; }
    float cn = fmaxf((float)(lo - lb), 1.0f);
    float s = bfc[o];
    for (int c = 0; c < DH; c++)
        s += (g_pool[g * DH + c] / cn) * Wfc[c * DOUT + o];
    out[g * DOUT + o] = s;
}

// ---------------- launch ------------------------------------------------------
extern "C" void kernel_launch(void* const* d_in, const int* in_sizes, int n_in,
                              void* d_out, int out_size)
{
    const float* x    = (const float*)d_in[0];
    const float* W1   = (const float*)d_in[1];
    const float* b1   = (const float*)d_in[2];
    const float* W2   = (const float*)d_in[3];
    const float* b2   = (const float*)d_in[4];
    const float* Wfc  = (const float*)d_in[5];
    const float* bfc  = (const float*)d_in[6];
    const int*   src  = (const int*)d_in[7];
    const int*   dst  = (const int*)d_in[8];
    const int*   batch= (const int*)d_in[9];
    float* out = (float*)d_out;

    const int nb_e = (EE + 255) / 256;
    const int nb_g = (NN + 127) / 128;
    const int nb_s = (NN * 32 + 255) / 256;   // one warp per node (6250, exact)

    // host-side handles, created once (no device memory involved)
    static cudaStream_t s_side = nullptr;
    static cudaEvent_t  ev_fork = nullptr, ev_dis = nullptr, ev_join = nullptr;
    if (s_side == nullptr) {
        cudaStreamCreateWithFlags(&s_side, cudaStreamNonBlocking);
        cudaEventCreateWithFlags(&ev_fork, cudaEventDisableTiming);
        cudaEventCreateWithFlags(&ev_dis,  cudaEventDisableTiming);
        cudaEventCreateWithFlags(&ev_join, cudaEventDisableTiming);
    }

    cudaFuncSetAttribute(k_gemm<DIN, false, false, 1>,
                         cudaFuncAttributeMaxDynamicSharedMemorySize, SMEM_TOT);
    cudaFuncSetAttribute(k_gemm<DH, true, true, 2>,
                         cudaFuncAttributeMaxDynamicSharedMemorySize, SMEM_TOT);

    k_prep<<<nb_e, 256>>>(W1, W2, dst);       // wsplit + pool zero + deg count

    // fork: the whole CSR build chain runs concurrently with k_dis + GEMM1
    cudaEventRecord(ev_fork, 0);
    cudaStreamWaitEvent(s_side, ev_fork, 0);
    k_scanA  <<<SCB, 256, 0, s_side>>>();
    k_scanC  <<<SCB, 256, 0, s_side>>>();
    k_reorder<<<nb_e, 256, 0, s_side>>>(src, dst);

    // main: dis (only g_ncnt needed) then GEMM1
    k_dis<<<SCB, 256>>>();
    cudaEventRecord(ev_dis, 0);               // last main-stream g_ncnt reader
    k_gemm<DIN, false, false, 1><<<nb_g, 256, SMEM_TOT>>>(x, b1);

    // side: zero ncnt after BOTH scanC (side order) and k_dis (event edge)
    cudaStreamWaitEvent(s_side, ev_dis, 0);
    k_zero_ncnt<<<SCB, 256, 0, s_side>>>();
    cudaEventRecord(ev_join, s_side);

    // join: scatter1 needs g_noff/g_esrc
    cudaStreamWaitEvent(0, ev_join, 0);
    k_scatter_csr<false><<<nb_s, 256>>>(b2, batch);

    // layer 2 (scatter fused with relu+bias+pool, block-aggregated atomics)
    k_gemm<DH, true, true, 2><<<nb_g, 256, SMEM_TOT>>>(nullptr, b1);
    k_scatter_csr<true><<<nb_s, 256>>>(b2, batch);

    k_fc<<<1, 128>>>(Wfc, bfc, batch, out);
}